// round 3
// baseline (speedup 1.0000x reference)
#include <cuda_runtime.h>
#include <math.h>

// ---------------------------------------------------------------------------
// Problem dims (fixed by the dataset)
// ---------------------------------------------------------------------------
#define Bn 8
#define H 64
#define W 128
#define HW (H * W)            // 8192
#define C1CH 96               // tenOne / tenTwo channels
#define HIN 32
#define WIN 64
#define HWIN (HIN * WIN)      // 2048
#define PREVC 661

#define FEAT_C 629
#define FEAT_STRIDE (FEAT_C * HW)   // per-batch stride of feat, 5152768

// channel offsets inside final feat (concats prepend):
// [c5(32) | c4(64) | c3(96) | c2(128) | c1(128) | vol(81) | tenOne(96) | flow(2) | upfeat(2)]
#define OFF_C5   0
#define OFF_C4   32
#define OFF_C3   96
#define OFF_C2   192
#define OFF_C1   320
#define OFF_VOL  448
#define OFF_T1   529
#define OFF_FLOW 625
#define OFF_UPF  627

// scratch: warped tenTwo
__device__ float g_warped[(size_t)Bn * C1CH * HW];

// ---------------------------------------------------------------------------
// ConvTranspose2d(k=4, s=2, p=1), Cout = 2.  out[o] += in[i]*w[k], o = 2i-1+k.
// For each output coord there are exactly 2 (i,k) pairs per axis.
// Weight layout: (Cin, 2, 4, 4).
// ---------------------------------------------------------------------------
__global__ void upconv_kernel(const float* __restrict__ in,
                              const float* __restrict__ w,
                              const float* __restrict__ bias,
                              float* __restrict__ out,   // feat slice, batch-0 channel ptr
                              int Cin)
{
    int gid = blockIdx.x * blockDim.x + threadIdx.x;
    if (gid >= Bn * HW) return;
    int b = gid / HW;
    int pix = gid - b * HW;
    int y = pix / W, x = pix - (pix / W) * W;

    int iy0 = y >> 1,                      ky0 = 1 + (y & 1);
    int iy1 = (y >> 1) + ((y & 1) ? 1 : -1), ky1 = (y & 1) ? 0 : 3;
    int ix0 = x >> 1,                      kx0 = 1 + (x & 1);
    int ix1 = (x >> 1) + ((x & 1) ? 1 : -1), kx1 = (x & 1) ? 0 : 3;
    bool vy1 = (unsigned)iy1 < HIN;
    bool vx1 = (unsigned)ix1 < WIN;

    float a0 = bias[0], a1 = bias[1];
    const float* pin = in + (size_t)b * Cin * HWIN;
    int w00i = ky0 * 4 + kx0, w01i = ky0 * 4 + kx1;
    int w10i = ky1 * 4 + kx0, w11i = ky1 * 4 + kx1;
    int p00 = iy0 * WIN + ix0, p01 = iy0 * WIN + ix1;
    int p10 = iy1 * WIN + ix0, p11 = iy1 * WIN + ix1;

    for (int ci = 0; ci < Cin; ci++) {
        const float* p = pin + (size_t)ci * HWIN;
        const float* wc = w + (size_t)ci * 32;
        float v = p[p00];
        a0 += v * wc[w00i];       a1 += v * wc[16 + w00i];
        if (vx1)        { float u = p[p01]; a0 += u * wc[w01i]; a1 += u * wc[16 + w01i]; }
        if (vy1)        { float u = p[p10]; a0 += u * wc[w10i]; a1 += u * wc[16 + w10i]; }
        if (vy1 && vx1) { float u = p[p11]; a0 += u * wc[w11i]; a1 += u * wc[16 + w11i]; }
    }
    out[(size_t)b * FEAT_STRIDE + pix]      = a0;
    out[(size_t)b * FEAT_STRIDE + HW + pix] = a1;
}

// ---------------------------------------------------------------------------
// Copy tenOne into its feat slice (float4 vectorized; batches contiguous)
// ---------------------------------------------------------------------------
__global__ void copy_t1_kernel(const float* __restrict__ t1, float* __restrict__ feat)
{
    size_t i = (size_t)blockIdx.x * blockDim.x + threadIdx.x;
    const size_t n4 = (size_t)Bn * C1CH * HW / 4;
    if (i >= n4) return;
    const size_t per = (size_t)C1CH * HW / 4;
    size_t b = i / per, r = i - b * per;
    float4 v = ((const float4*)t1)[i];
    ((float4*)(feat + b * (size_t)FEAT_STRIDE + (size_t)OFF_T1 * HW))[r] = v;
}

// ---------------------------------------------------------------------------
// Bilinear warp of tenTwo by flow*1.25 (zeros padding, align_corners=True)
// flow is read from the feat buffer (channels OFF_FLOW, OFF_FLOW+1)
// ---------------------------------------------------------------------------
__global__ void warp_kernel(const float* __restrict__ tenTwo, const float* __restrict__ feat)
{
    int gid = blockIdx.x * blockDim.x + threadIdx.x;
    if (gid >= Bn * HW) return;
    int b = gid / HW;
    int pix = gid - b * HW;
    int y = pix / W, x = pix - (pix / W) * W;

    const float* fl = feat + (size_t)b * FEAT_STRIDE + (size_t)OFF_FLOW * HW + pix;
    float px = (float)x + fl[0]  * 1.25f;
    float py = (float)y + fl[HW] * 1.25f;
    float fx = floorf(px), fy = floorf(py);
    float wx = px - fx, wy = py - fy;
    int ix0 = (int)fx, iy0 = (int)fy;
    int ix1 = ix0 + 1, iy1 = iy0 + 1;
    bool vx0 = (unsigned)ix0 < W, vx1 = (unsigned)ix1 < W;
    bool vy0 = (unsigned)iy0 < H, vy1 = (unsigned)iy1 < H;
    float w00 = (1.f - wy) * (1.f - wx), w01 = (1.f - wy) * wx;
    float w10 = wy * (1.f - wx),         w11 = wy * wx;
    int o00 = iy0 * W + ix0, o01 = iy0 * W + ix1;
    int o10 = iy1 * W + ix0, o11 = iy1 * W + ix1;

    const float* t = tenTwo + (size_t)b * C1CH * HW;
    float* o = g_warped + (size_t)b * C1CH * HW + pix;
    for (int c = 0; c < C1CH; c++) {
        const float* tc = t + (size_t)c * HW;
        float v = 0.f;
        if (vy0 && vx0) v += tc[o00] * w00;
        if (vy0 && vx1) v += tc[o01] * w01;
        if (vy1 && vx0) v += tc[o10] * w10;
        if (vy1 && vx1) v += tc[o11] * w11;
        o[(size_t)c * HW] = v;
    }
}

// ---------------------------------------------------------------------------
// 81-tap correlation: vol[d] = leaky(mean_c f1[c,y,x] * warped[c, y+dy-4, x+dx-4])
// block = 32x4 pixel tile, 128 threads, 81 accumulators per thread.
// ---------------------------------------------------------------------------
__global__ __launch_bounds__(128) void corr_kernel(const float* __restrict__ tenOne,
                                                   float* __restrict__ feat)
{
    __shared__ float s_f1[4][32];
    __shared__ float s_w2[12][40];
    int tid = threadIdx.x;
    int tx = tid & 31, ty = tid >> 5;
    int x0 = blockIdx.x * 32, y0 = blockIdx.y * 4, b = blockIdx.z;

    float acc[81];
#pragma unroll
    for (int d = 0; d < 81; d++) acc[d] = 0.f;

    const float* f1 = tenOne + (size_t)b * C1CH * HW;
    const float* f2 = g_warped + (size_t)b * C1CH * HW;

    for (int c = 0; c < C1CH; c++) {
        const float* f1c = f1 + (size_t)c * HW;
        const float* f2c = f2 + (size_t)c * HW;
        __syncthreads();
        s_f1[ty][tx] = f1c[(y0 + ty) * W + x0 + tx];
#pragma unroll
        for (int i = 0; i < 4; i++) {
            int idx = tid + i * 128;
            if (idx < 480) {
                int r = idx / 40, cc = idx - (idx / 40) * 40;
                int gy = y0 - 4 + r, gx = x0 - 4 + cc;
                float v = 0.f;
                if ((unsigned)gy < H && (unsigned)gx < W) v = f2c[gy * W + gx];
                s_w2[r][cc] = v;
            }
        }
        __syncthreads();
        float a = s_f1[ty][tx];
#pragma unroll
        for (int dy = 0; dy < 9; dy++)
#pragma unroll
            for (int dx = 0; dx < 9; dx++)
                acc[dy * 9 + dx] += a * s_w2[ty + dy][tx + dx];
    }

    float* o = feat + (size_t)b * FEAT_STRIDE + (size_t)OFF_VOL * HW + (y0 + ty) * W + x0 + tx;
    const float inv = 1.f / 96.f;
#pragma unroll
    for (int d = 0; d < 81; d++) {
        float v = acc[d] * inv;
        o[(size_t)d * HW] = (v >= 0.f) ? v : 0.1f * v;
    }
}

// ---------------------------------------------------------------------------
// Direct 3x3 conv (pad 1), leaky ReLU.
// 256 threads, 64x16 output tile, each thread: 1x4 pixel strip x COUT_BLK couts.
// grid: (coutGroups, 8 tiles, B).  Cout groups fastest -> concurrent blocks
// share input tiles via L2.
// ---------------------------------------------------------------------------
template <int COUT_BLK>
__global__ __launch_bounds__(256) void conv3x3_kernel(
    const float* __restrict__ in,    // batch-0 ptr at input channel offset
    const float* __restrict__ w,     // (CoutTotal, Cin, 3, 3)
    const float* __restrict__ bias,
    float* __restrict__ out,         // batch-0 ptr at output channel offset
    int Cin, int inStride, int outStride)
{
    __shared__ float s_in[18][66];
    __shared__ float s_w[COUT_BLK * 9];
    const int tid = threadIdx.x;
    const int tx = tid & 15, ty = tid >> 4;
    const int g = blockIdx.x;
    const int tileX = blockIdx.y & 1, tileY = blockIdx.y >> 1;
    const int b = blockIdx.z;
    const int x0 = tileX * 64, y0 = tileY * 16;

    const float* inB = in + (size_t)b * inStride;
    float acc[COUT_BLK][4];
#pragma unroll
    for (int c = 0; c < COUT_BLK; c++)
#pragma unroll
        for (int p = 0; p < 4; p++) acc[c][p] = 0.f;

    for (int ci = 0; ci < Cin; ci++) {
        const float* ch = inB + (size_t)ci * HW;
#pragma unroll
        for (int i = 0; i < 5; i++) {
            int idx = tid + i * 256;
            if (idx < 18 * 66) {
                int r = idx / 66, c = idx - (idx / 66) * 66;
                int gy = y0 - 1 + r, gx = x0 - 1 + c;
                float v = 0.f;
                if ((unsigned)gy < H && (unsigned)gx < W) v = ch[gy * W + gx];
                s_in[r][c] = v;
            }
        }
        if (tid < COUT_BLK * 9)
            s_w[tid] = w[((size_t)(g * COUT_BLK + tid / 9) * Cin + ci) * 9 + tid % 9];
        __syncthreads();

        float r0[6], r1[6], r2[6];
#pragma unroll
        for (int k = 0; k < 6; k++) {
            r0[k] = s_in[ty][tx * 4 + k];
            r1[k] = s_in[ty + 1][tx * 4 + k];
            r2[k] = s_in[ty + 2][tx * 4 + k];
        }
#pragma unroll
        for (int co = 0; co < COUT_BLK; co++) {
            float w0 = s_w[co * 9 + 0], w1v = s_w[co * 9 + 1], w2v = s_w[co * 9 + 2];
            float w3v = s_w[co * 9 + 3], w4v = s_w[co * 9 + 4], w5v = s_w[co * 9 + 5];
            float w6v = s_w[co * 9 + 6], w7v = s_w[co * 9 + 7], w8v = s_w[co * 9 + 8];
#pragma unroll
            for (int p = 0; p < 4; p++) {
                float s = acc[co][p];
                s += w0  * r0[p]; s += w1v * r0[p + 1]; s += w2v * r0[p + 2];
                s += w3v * r1[p]; s += w4v * r1[p + 1]; s += w5v * r1[p + 2];
                s += w6v * r2[p]; s += w7v * r2[p + 1]; s += w8v * r2[p + 2];
                acc[co][p] = s;
            }
        }
        __syncthreads();
    }

#pragma unroll
    for (int co = 0; co < COUT_BLK; co++) {
        float bi = bias[g * COUT_BLK + co];
        float* o = out + (size_t)b * outStride + (size_t)(g * COUT_BLK + co) * HW
                 + (y0 + ty) * W + x0 + tx * 4;
#pragma unroll
        for (int p = 0; p < 4; p++) {
            float v = acc[co][p] + bi;
            o[p] = (v >= 0.f) ? v : 0.1f * v;
        }
    }
}

// ---------------------------------------------------------------------------
// Launch
// ---------------------------------------------------------------------------
extern "C" void kernel_launch(void* const* d_in, const int* in_sizes, int n_in,
                              void* d_out, int out_size)
{
    (void)in_sizes; (void)n_in; (void)out_size;
    const float* tenOne    = (const float*)d_in[0];
    const float* tenTwo    = (const float*)d_in[1];
    const float* prev_flow = (const float*)d_in[2];
    const float* prev_feat = (const float*)d_in[3];
    const float* w_upflow  = (const float*)d_in[4];
    const float* b_upflow  = (const float*)d_in[5];
    const float* w_upfeat  = (const float*)d_in[6];
    const float* b_upfeat  = (const float*)d_in[7];
    const float* w1 = (const float*)d_in[8];   const float* b1 = (const float*)d_in[9];
    const float* w2 = (const float*)d_in[10];  const float* b2 = (const float*)d_in[11];
    const float* w3 = (const float*)d_in[12];  const float* b3 = (const float*)d_in[13];
    const float* w4 = (const float*)d_in[14];  const float* b4 = (const float*)d_in[15];
    const float* w5 = (const float*)d_in[16];  const float* b5 = (const float*)d_in[17];
    const float* w6 = (const float*)d_in[18];  const float* b6 = (const float*)d_in[19];

    float* flow = (float*)d_out;                       // (B, 2, H, W)
    float* feat = flow + (size_t)Bn * 2 * HW;          // (B, 629, H, W)

    const int NPIX = Bn * HW;

    // 1. upsample flow -> feat[:, 625:627]
    upconv_kernel<<<(NPIX + 255) / 256, 256>>>(prev_flow, w_upflow, b_upflow,
                                               feat + (size_t)OFF_FLOW * HW, 2);
    // 2. upsample feat -> feat[:, 627:629]
    upconv_kernel<<<(NPIX + 255) / 256, 256>>>(prev_feat, w_upfeat, b_upfeat,
                                               feat + (size_t)OFF_UPF * HW, PREVC);
    // 3. tenOne -> feat[:, 529:625]
    {
        size_t n4 = (size_t)Bn * C1CH * HW / 4;
        copy_t1_kernel<<<(unsigned)((n4 + 255) / 256), 256>>>(tenOne, feat);
    }
    // 4. warp tenTwo with flow*1.25 -> g_warped
    warp_kernel<<<(NPIX + 255) / 256, 256>>>(tenTwo, feat);
    // 5. correlation + leaky -> feat[:, 448:529]
    corr_kernel<<<dim3(W / 32, H / 4, Bn), 128>>>(tenOne, feat);

    // 6. dense conv tower (each writes its slice; inputs are suffixes of feat)
    conv3x3_kernel<8><<<dim3(128 / 8, 8, Bn), 256>>>(
        feat + (size_t)OFF_VOL * HW, w1, b1, feat + (size_t)OFF_C1 * HW,
        181, FEAT_STRIDE, FEAT_STRIDE);
    conv3x3_kernel<8><<<dim3(128 / 8, 8, Bn), 256>>>(
        feat + (size_t)OFF_C1 * HW, w2, b2, feat + (size_t)OFF_C2 * HW,
        309, FEAT_STRIDE, FEAT_STRIDE);
    conv3x3_kernel<8><<<dim3(96 / 8, 8, Bn), 256>>>(
        feat + (size_t)OFF_C2 * HW, w3, b3, feat + (size_t)OFF_C3 * HW,
        437, FEAT_STRIDE, FEAT_STRIDE);
    conv3x3_kernel<8><<<dim3(64 / 8, 8, Bn), 256>>>(
        feat + (size_t)OFF_C3 * HW, w4, b4, feat + (size_t)OFF_C4 * HW,
        533, FEAT_STRIDE, FEAT_STRIDE);
    conv3x3_kernel<8><<<dim3(32 / 8, 8, Bn), 256>>>(
        feat + (size_t)OFF_C4 * HW, w5, b5, feat + (size_t)OFF_C5 * HW,
        597, FEAT_STRIDE, FEAT_STRIDE);
    // conv6 -> flow output (Cout = 2)
    conv3x3_kernel<2><<<dim3(1, 8, Bn), 256>>>(
        feat + (size_t)OFF_C5 * HW, w6, b6, flow,
        629, FEAT_STRIDE, 2 * HW);
}

// round 5
// speedup vs baseline: 1.3964x; 1.3964x over previous
#include <cuda_runtime.h>
#include <math.h>
#include <stdint.h>

// ---------------------------------------------------------------------------
// Problem dims (fixed by the dataset)
// ---------------------------------------------------------------------------
#define Bn 8
#define H 64
#define W 128
#define HW (H * W)            // 8192
#define C1CH 96               // tenOne / tenTwo channels
#define HIN 32
#define WIN 64
#define HWIN (HIN * WIN)      // 2048
#define PREVC 661

#define FEAT_C 629
#define FEAT_STRIDE (FEAT_C * HW)   // per-batch stride of feat

// channel offsets inside final feat (concats prepend):
// [c5(32) | c4(64) | c3(96) | c2(128) | c1(128) | vol(81) | tenOne(96) | flow(2) | upfeat(2)]
#define OFF_C5   0
#define OFF_C4   32
#define OFF_C3   96
#define OFF_C2   192
#define OFF_C1   320
#define OFF_VOL  448
#define OFF_T1   529
#define OFF_FLOW 625
#define OFF_UPF  627

// scratch: warped tenTwo
__device__ float g_warped[(size_t)Bn * C1CH * HW];

// pre-packed tf32 weight fragments (hi+lo blocks per 32-K chunk)
// chunks per stage: 51, 87, 123, 150, 168
#define APACK_OFF1 0
#define APACK_OFF2 417792      // + 2*51*128*32
#define APACK_OFF3 1130496     // + 2*87*128*32
#define APACK_OFF4 1886208     // + 2*123*96*32
#define APACK_OFF5 2500608     // + 2*150*64*32
#define APACK_TOTAL 2844672    // + 2*168*32*32
__device__ uint32_t g_Apack[APACK_TOTAL];

// ---------------------------------------------------------------------------
// helpers
// ---------------------------------------------------------------------------
__device__ __forceinline__ uint32_t f2tf32(float f) {
    uint32_t r;
    asm("cvt.rna.tf32.f32 %0, %1;" : "=r"(r) : "f"(f));
    return r;
}

#define MMA_TF32(c, a, b0v, b1v) \
    asm volatile( \
        "mma.sync.aligned.m16n8k8.row.col.f32.tf32.tf32.f32 " \
        "{%0,%1,%2,%3}, {%4,%5,%6,%7}, {%8,%9}, {%0,%1,%2,%3};" \
        : "+f"((c)[0]), "+f"((c)[1]), "+f"((c)[2]), "+f"((c)[3]) \
        : "r"((a).x), "r"((a).y), "r"((a).z), "r"((a).w), \
          "r"(b0v), "r"(b1v))

// ---------------------------------------------------------------------------
// ConvTranspose2d(k=4, s=2, p=1), Cout = 2
// ---------------------------------------------------------------------------
__global__ void upconv_kernel(const float* __restrict__ in,
                              const float* __restrict__ w,
                              const float* __restrict__ bias,
                              float* __restrict__ out, int Cin)
{
    int gid = blockIdx.x * blockDim.x + threadIdx.x;
    if (gid >= Bn * HW) return;
    int b = gid / HW;
    int pix = gid - b * HW;
    int y = pix / W, x = pix - (pix / W) * W;

    int iy0 = y >> 1,                        ky0 = 1 + (y & 1);
    int iy1 = (y >> 1) + ((y & 1) ? 1 : -1), ky1 = (y & 1) ? 0 : 3;
    int ix0 = x >> 1,                        kx0 = 1 + (x & 1);
    int ix1 = (x >> 1) + ((x & 1) ? 1 : -1), kx1 = (x & 1) ? 0 : 3;
    bool vy1 = (unsigned)iy1 < HIN;
    bool vx1 = (unsigned)ix1 < WIN;

    float a0 = bias[0], a1 = bias[1];
    const float* pin = in + (size_t)b * Cin * HWIN;
    int w00i = ky0 * 4 + kx0, w01i = ky0 * 4 + kx1;
    int w10i = ky1 * 4 + kx0, w11i = ky1 * 4 + kx1;
    int p00 = iy0 * WIN + ix0, p01 = iy0 * WIN + ix1;
    int p10 = iy1 * WIN + ix0, p11 = iy1 * WIN + ix1;

    for (int ci = 0; ci < Cin; ci++) {
        const float* p = pin + (size_t)ci * HWIN;
        const float* wc = w + (size_t)ci * 32;
        float v = p[p00];
        a0 += v * wc[w00i];       a1 += v * wc[16 + w00i];
        if (vx1)        { float u = p[p01]; a0 += u * wc[w01i]; a1 += u * wc[16 + w01i]; }
        if (vy1)        { float u = p[p10]; a0 += u * wc[w10i]; a1 += u * wc[16 + w10i]; }
        if (vy1 && vx1) { float u = p[p11]; a0 += u * wc[w11i]; a1 += u * wc[16 + w11i]; }
    }
    out[(size_t)b * FEAT_STRIDE + pix]      = a0;
    out[(size_t)b * FEAT_STRIDE + HW + pix] = a1;
}

__global__ void copy_t1_kernel(const float* __restrict__ t1, float* __restrict__ feat)
{
    size_t i = (size_t)blockIdx.x * blockDim.x + threadIdx.x;
    const size_t n4 = (size_t)Bn * C1CH * HW / 4;
    if (i >= n4) return;
    const size_t per = (size_t)C1CH * HW / 4;
    size_t b = i / per, r = i - b * per;
    float4 v = ((const float4*)t1)[i];
    ((float4*)(feat + b * (size_t)FEAT_STRIDE + (size_t)OFF_T1 * HW))[r] = v;
}

__global__ void warp_kernel(const float* __restrict__ tenTwo, const float* __restrict__ feat)
{
    int gid = blockIdx.x * blockDim.x + threadIdx.x;
    if (gid >= Bn * HW) return;
    int b = gid / HW;
    int pix = gid - b * HW;
    int y = pix / W, x = pix - (pix / W) * W;

    const float* fl = feat + (size_t)b * FEAT_STRIDE + (size_t)OFF_FLOW * HW + pix;
    float px = (float)x + fl[0]  * 1.25f;
    float py = (float)y + fl[HW] * 1.25f;
    float fx = floorf(px), fy = floorf(py);
    float wx = px - fx, wy = py - fy;
    int ix0 = (int)fx, iy0 = (int)fy;
    int ix1 = ix0 + 1, iy1 = iy0 + 1;
    bool vx0 = (unsigned)ix0 < W, vx1 = (unsigned)ix1 < W;
    bool vy0 = (unsigned)iy0 < H, vy1 = (unsigned)iy1 < H;
    float w00 = (1.f - wy) * (1.f - wx), w01 = (1.f - wy) * wx;
    float w10 = wy * (1.f - wx),         w11 = wy * wx;
    int o00 = iy0 * W + ix0, o01 = iy0 * W + ix1;
    int o10 = iy1 * W + ix0, o11 = iy1 * W + ix1;

    const float* t = tenTwo + (size_t)b * C1CH * HW;
    float* o = g_warped + (size_t)b * C1CH * HW + pix;
    for (int c = 0; c < C1CH; c++) {
        const float* tc = t + (size_t)c * HW;
        float v = 0.f;
        if (vy0 && vx0) v += tc[o00] * w00;
        if (vy0 && vx1) v += tc[o01] * w01;
        if (vy1 && vx0) v += tc[o10] * w10;
        if (vy1 && vx1) v += tc[o11] * w11;
        o[(size_t)c * HW] = v;
    }
}

__global__ __launch_bounds__(128) void corr_kernel(const float* __restrict__ tenOne,
                                                   float* __restrict__ feat)
{
    __shared__ float s_f1[4][32];
    __shared__ float s_w2[12][40];
    int tid = threadIdx.x;
    int tx = tid & 31, ty = tid >> 5;
    int x0 = blockIdx.x * 32, y0 = blockIdx.y * 4, b = blockIdx.z;

    float acc[81];
#pragma unroll
    for (int d = 0; d < 81; d++) acc[d] = 0.f;

    const float* f1 = tenOne + (size_t)b * C1CH * HW;
    const float* f2 = g_warped + (size_t)b * C1CH * HW;

    for (int c = 0; c < C1CH; c++) {
        const float* f1c = f1 + (size_t)c * HW;
        const float* f2c = f2 + (size_t)c * HW;
        __syncthreads();
        s_f1[ty][tx] = f1c[(y0 + ty) * W + x0 + tx];
#pragma unroll
        for (int i = 0; i < 4; i++) {
            int idx = tid + i * 128;
            if (idx < 480) {
                int r = idx / 40, cc = idx - (idx / 40) * 40;
                int gy = y0 - 4 + r, gx = x0 - 4 + cc;
                float v = 0.f;
                if ((unsigned)gy < H && (unsigned)gx < W) v = f2c[gy * W + gx];
                s_w2[r][cc] = v;
            }
        }
        __syncthreads();
        float a = s_f1[ty][tx];
#pragma unroll
        for (int dy = 0; dy < 9; dy++)
#pragma unroll
            for (int dx = 0; dx < 9; dx++)
                acc[dy * 9 + dx] += a * s_w2[ty + dy][tx + dx];
    }

    float* o = feat + (size_t)b * FEAT_STRIDE + (size_t)OFF_VOL * HW + (y0 + ty) * W + x0 + tx;
    const float inv = 1.f / 96.f;
#pragma unroll
    for (int d = 0; d < 81; d++) {
        float v = acc[d] * inv;
        o[(size_t)d * HW] = (v >= 0.f) ? v : 0.1f * v;
    }
}

// ---------------------------------------------------------------------------
// FFMA direct 3x3 conv (kept for conv6, Cout=2)
// ---------------------------------------------------------------------------
template <int COUT_BLK>
__global__ __launch_bounds__(256) void conv3x3_kernel(
    const float* __restrict__ in, const float* __restrict__ w,
    const float* __restrict__ bias, float* __restrict__ out,
    int Cin, int inStride, int outStride)
{
    __shared__ float s_in[18][66];
    __shared__ float s_w[COUT_BLK * 9];
    const int tid = threadIdx.x;
    const int tx = tid & 15, ty = tid >> 4;
    const int g = blockIdx.x;
    const int tileX = blockIdx.y & 1, tileY = blockIdx.y >> 1;
    const int b = blockIdx.z;
    const int x0 = tileX * 64, y0 = tileY * 16;

    const float* inB = in + (size_t)b * inStride;
    float acc[COUT_BLK][4];
#pragma unroll
    for (int c = 0; c < COUT_BLK; c++)
#pragma unroll
        for (int p = 0; p < 4; p++) acc[c][p] = 0.f;

    for (int ci = 0; ci < Cin; ci++) {
        const float* ch = inB + (size_t)ci * HW;
#pragma unroll
        for (int i = 0; i < 5; i++) {
            int idx = tid + i * 256;
            if (idx < 18 * 66) {
                int r = idx / 66, c = idx - (idx / 66) * 66;
                int gy = y0 - 1 + r, gx = x0 - 1 + c;
                float v = 0.f;
                if ((unsigned)gy < H && (unsigned)gx < W) v = ch[gy * W + gx];
                s_in[r][c] = v;
            }
        }
        if (tid < COUT_BLK * 9)
            s_w[tid] = w[((size_t)(g * COUT_BLK + tid / 9) * Cin + ci) * 9 + tid % 9];
        __syncthreads();

        float r0[6], r1[6], r2[6];
#pragma unroll
        for (int k = 0; k < 6; k++) {
            r0[k] = s_in[ty][tx * 4 + k];
            r1[k] = s_in[ty + 1][tx * 4 + k];
            r2[k] = s_in[ty + 2][tx * 4 + k];
        }
#pragma unroll
        for (int co = 0; co < COUT_BLK; co++) {
            float w0 = s_w[co * 9 + 0], w1v = s_w[co * 9 + 1], w2v = s_w[co * 9 + 2];
            float w3v = s_w[co * 9 + 3], w4v = s_w[co * 9 + 4], w5v = s_w[co * 9 + 5];
            float w6v = s_w[co * 9 + 6], w7v = s_w[co * 9 + 7], w8v = s_w[co * 9 + 8];
#pragma unroll
            for (int p = 0; p < 4; p++) {
                float s = acc[co][p];
                s += w0  * r0[p]; s += w1v * r0[p + 1]; s += w2v * r0[p + 2];
                s += w3v * r1[p]; s += w4v * r1[p + 1]; s += w5v * r1[p + 2];
                s += w6v * r2[p]; s += w7v * r2[p + 1]; s += w8v * r2[p + 2];
                acc[co][p] = s;
            }
        }
        __syncthreads();
    }

#pragma unroll
    for (int co = 0; co < COUT_BLK; co++) {
        float bi = bias[g * COUT_BLK + co];
        float* o = out + (size_t)b * outStride + (size_t)(g * COUT_BLK + co) * HW
                 + (y0 + ty) * W + x0 + tx * 4;
#pragma unroll
        for (int p = 0; p < 4; p++) {
            float v = acc[co][p] + bi;
            o[p] = (v >= 0.f) ? v : 0.1f * v;
        }
    }
}

// ---------------------------------------------------------------------------
// Weight pre-pack into per-fragment tf32 order (hi block + lo block per chunk)
// chunk layout: [kt][hi/lo][(ks*MFT + mf)*128 + lane*4 + r]
//   m = mf*16 + (lane>>2) + 8*(r&1),  k = kt*32 + ks*8 + (lane&3) + 4*(r>>1)
// ---------------------------------------------------------------------------
__global__ void pack_weights_kernel(const float* __restrict__ w, uint32_t* __restrict__ dst,
                                    int Cin, int Cout, int nChunks)
{
    int idx = blockIdx.x * blockDim.x + threadIdx.x;
    int per = Cout * 32;
    if (idx >= nChunks * per) return;
    int kt = idx / per, j = idx - kt * per;
    int ks = j / (Cout * 8);
    int j2 = j - ks * (Cout * 8);
    int mf = j2 >> 7, q = j2 & 127;
    int lane = q >> 2, r = q & 3;
    int m = mf * 16 + (lane >> 2) + 8 * (r & 1);
    int k = kt * 32 + ks * 8 + (lane & 3) + 4 * (r >> 1);
    int K = Cin * 9;
    float v = (m < Cout && k < K) ? w[(size_t)m * K + k] : 0.f;
    uint32_t hi = f2tf32(v);
    float lo = v - __uint_as_float(hi);
    dst[(size_t)(kt * 2) * per + j]     = hi;
    dst[(size_t)(kt * 2 + 1) * per + j] = f2tf32(lo);
}

// ---------------------------------------------------------------------------
// Implicit-GEMM 3x3 conv via mma.sync m16n8k8 tf32 (3xTF32 split).
// CTA: M = Cout, N = NROWS*128 pixels. Warp tile 32x64. K-chunks of 32.
// ---------------------------------------------------------------------------
template <int Cin, int Cout, int MW, int NW, int NROWS, int THREADS>
__global__ __launch_bounds__(THREADS, 2) void conv_mma_kernel(
    const float* __restrict__ inBase,    // feat batch-0 ptr at input channel offset
    const uint32_t* __restrict__ Apack,  // g_Apack + stage offset
    const float* __restrict__ bias,
    float* __restrict__ outBase)         // feat batch-0 ptr at output channel offset
{
    constexpr int K   = Cin * 9;
    constexpr int nC  = (K + 31) / 32;
    constexpr int N   = NROWS * 128;
    constexpr int SBS = N + 8;              // stride mod 32 == 8 -> conflict-free frag reads
    constexpr int MFT = Cout / 16;
    constexpr int PER = Cout * 32;          // u32 per hi (or lo) chunk block

    extern __shared__ uint32_t sh[];
    uint32_t* sAhi = sh;
    uint32_t* sAlo = sh + PER;
    uint32_t* sBhi = sh + 2 * PER;
    uint32_t* sBlo = sBhi + 32 * SBS;

    const int tid = threadIdx.x, lane = tid & 31, wrp = tid >> 5;
    const int wm0 = (wrp / NW) * 32, wn0 = (wrp % NW) * 64;
    const int yBase = blockIdx.x * NROWS, b = blockIdx.y;
    const float* inB = inBase + (size_t)b * FEAT_STRIDE;

    float c[2][8][4];
#pragma unroll
    for (int mi = 0; mi < 2; mi++)
#pragma unroll
        for (int ni = 0; ni < 8; ni++)
#pragma unroll
            for (int p = 0; p < 4; p++) c[mi][ni][p] = 0.f;

    for (int kt = 0; kt < nC; kt++) {
        __syncthreads();
        // --- stage A: linear copy of pre-fragmented hi+lo chunk blocks ---
        {
            const float4* src = (const float4*)(Apack + (size_t)kt * 2 * PER);
            float4* dst = (float4*)sAhi;     // sAlo is contiguous after sAhi
#pragma unroll 2
            for (int i = tid; i < Cout * 16; i += THREADS) dst[i] = src[i];
        }
        // --- stage B: im2col + tf32 hi/lo split ---
        for (int e = tid; e < 32 * N; e += THREADS) {
            int kk = e / N;                  // N is power of two
            int n  = e & (N - 1);
            int k  = kt * 32 + kk;
            int ci = k / 9, r = k - ci * 9;
            int gy = yBase + (n >> 7) + r / 3 - 1;
            int gx = (n & 127) + (r - (r / 3) * 3) - 1;
            float v = 0.f;
            if (k < K && (unsigned)gy < H && (unsigned)gx < W)
                v = __ldg(inB + (size_t)ci * HW + gy * W + gx);
            uint32_t hi = f2tf32(v);
            float lo = v - __uint_as_float(hi);
            sBhi[kk * SBS + n] = hi;
            sBlo[kk * SBS + n] = f2tf32(lo);
        }
        __syncthreads();
        // --- compute: 4 k-steps of m16n8k8, 3xTF32 ---
#pragma unroll
        for (int ks = 0; ks < 4; ks++) {
            uint4 ah[2], al[2];
            const uint4* pah = (const uint4*)sAhi;
            const uint4* pal = (const uint4*)sAlo;
#pragma unroll
            for (int mi = 0; mi < 2; mi++) {
                int fi = (ks * MFT + (wm0 >> 4) + mi) * 32 + lane;
                ah[mi] = pah[fi];
                al[mi] = pal[fi];
            }
            const int kb = ks * 8 + (lane & 3);
            const uint32_t* pbh = sBhi + kb * SBS + wn0 + (lane >> 2);
            const uint32_t* pbl = sBlo + kb * SBS + wn0 + (lane >> 2);
#pragma unroll
            for (int ni = 0; ni < 8; ni++) {
                uint32_t bh0 = pbh[ni * 8], bh1 = pbh[4 * SBS + ni * 8];
                uint32_t bl0 = pbl[ni * 8], bl1 = pbl[4 * SBS + ni * 8];
#pragma unroll
                for (int mi = 0; mi < 2; mi++) {
                    MMA_TF32(c[mi][ni], ah[mi], bh0, bh1);
                    MMA_TF32(c[mi][ni], al[mi], bh0, bh1);
                    MMA_TF32(c[mi][ni], ah[mi], bl0, bl1);
                }
            }
        }
    }

    // --- epilogue: bias + leaky, float2 stores ---
    const int q = lane & 3, g = lane >> 2;
    float* outB = outBase + (size_t)b * FEAT_STRIDE;
#pragma unroll
    for (int mi = 0; mi < 2; mi++) {
        int m0 = wm0 + mi * 16 + g;
        float bl = __ldg(bias + m0), bh = __ldg(bias + m0 + 8);
        float* o0 = outB + (size_t)m0 * HW;
        float* o1 = o0 + 8 * HW;
#pragma unroll
        for (int ni = 0; ni < 8; ni++) {
            int n = wn0 + ni * 8 + 2 * q;
            int off = (yBase + (n >> 7)) * W + (n & 127);
            float v0 = c[mi][ni][0] + bl, v1 = c[mi][ni][1] + bl;
            float v2 = c[mi][ni][2] + bh, v3 = c[mi][ni][3] + bh;
            v0 = (v0 >= 0.f) ? v0 : 0.1f * v0;
            v1 = (v1 >= 0.f) ? v1 : 0.1f * v1;
            v2 = (v2 >= 0.f) ? v2 : 0.1f * v2;
            v3 = (v3 >= 0.f) ? v3 : 0.1f * v3;
            *(float2*)(o0 + off) = make_float2(v0, v1);
            *(float2*)(o1 + off) = make_float2(v2, v3);
        }
    }
}

// ---------------------------------------------------------------------------
// Launch
// ---------------------------------------------------------------------------
extern "C" void kernel_launch(void* const* d_in, const int* in_sizes, int n_in,
                              void* d_out, int out_size)
{
    (void)in_sizes; (void)n_in; (void)out_size;
    const float* tenOne    = (const float*)d_in[0];
    const float* tenTwo    = (const float*)d_in[1];
    const float* prev_flow = (const float*)d_in[2];
    const float* prev_feat = (const float*)d_in[3];
    const float* w_upflow  = (const float*)d_in[4];
    const float* b_upflow  = (const float*)d_in[5];
    const float* w_upfeat  = (const float*)d_in[6];
    const float* b_upfeat  = (const float*)d_in[7];
    const float* w1 = (const float*)d_in[8];   const float* b1 = (const float*)d_in[9];
    const float* w2 = (const float*)d_in[10];  const float* b2 = (const float*)d_in[11];
    const float* w3 = (const float*)d_in[12];  const float* b3 = (const float*)d_in[13];
    const float* w4 = (const float*)d_in[14];  const float* b4 = (const float*)d_in[15];
    const float* w5 = (const float*)d_in[16];  const float* b5 = (const float*)d_in[17];
    const float* w6 = (const float*)d_in[18];  const float* b6 = (const float*)d_in[19];

    float* flow = (float*)d_out;                       // (B, 2, H, W)
    float* feat = flow + (size_t)Bn * 2 * HW;          // (B, 629, H, W)

    uint32_t* apack;
    cudaGetSymbolAddress((void**)&apack, g_Apack);

    // smem sizes per stage (bytes)
    const int SM1 = (2 * 128 * 32 + 2 * 32 * 136) * 4;   // 67584
    const int SM3 = (2 * 96  * 32 + 2 * 32 * 136) * 4;   // 59392
    const int SM4 = (2 * 64  * 32 + 2 * 32 * 264) * 4;   // 83968
    const int SM5 = (2 * 32  * 32 + 2 * 32 * 264) * 4;   // 75776

    cudaFuncSetAttribute(conv_mma_kernel<181, 128, 4, 2, 1, 256>, cudaFuncAttributeMaxDynamicSharedMemorySize, SM1);
    cudaFuncSetAttribute(conv_mma_kernel<309, 128, 4, 2, 1, 256>, cudaFuncAttributeMaxDynamicSharedMemorySize, SM1);
    cudaFuncSetAttribute(conv_mma_kernel<437,  96, 3, 2, 1, 192>, cudaFuncAttributeMaxDynamicSharedMemorySize, SM3);
    cudaFuncSetAttribute(conv_mma_kernel<533,  64, 2, 4, 2, 256>, cudaFuncAttributeMaxDynamicSharedMemorySize, SM4);
    cudaFuncSetAttribute(conv_mma_kernel<597,  32, 1, 4, 2, 128>, cudaFuncAttributeMaxDynamicSharedMemorySize, SM5);

    const int NPIX = Bn * HW;

    // weight pre-pack (amortized; independent of activations)
    pack_weights_kernel<<<(51  * 128 * 32 + 255) / 256, 256>>>(w1, apack + APACK_OFF1, 181, 128, 51);
    pack_weights_kernel<<<(87  * 128 * 32 + 255) / 256, 256>>>(w2, apack + APACK_OFF2, 309, 128, 87);
    pack_weights_kernel<<<(123 * 96  * 32 + 255) / 256, 256>>>(w3, apack + APACK_OFF3, 437, 96, 123);
    pack_weights_kernel<<<(150 * 64  * 32 + 255) / 256, 256>>>(w4, apack + APACK_OFF4, 533, 64, 150);
    pack_weights_kernel<<<(168 * 32  * 32 + 255) / 256, 256>>>(w5, apack + APACK_OFF5, 597, 32, 168);

    // 1-2. upsampled flow / feat
    upconv_kernel<<<(NPIX + 255) / 256, 256>>>(prev_flow, w_upflow, b_upflow,
                                               feat + (size_t)OFF_FLOW * HW, 2);
    upconv_kernel<<<(NPIX + 255) / 256, 256>>>(prev_feat, w_upfeat, b_upfeat,
                                               feat + (size_t)OFF_UPF * HW, PREVC);
    // 3. tenOne -> feat
    {
        size_t n4 = (size_t)Bn * C1CH * HW / 4;
        copy_t1_kernel<<<(unsigned)((n4 + 255) / 256), 256>>>(tenOne, feat);
    }
    // 4. warp tenTwo
    warp_kernel<<<(NPIX + 255) / 256, 256>>>(tenTwo, feat);
    // 5. correlation
    corr_kernel<<<dim3(W / 32, H / 4, Bn), 128>>>(tenOne, feat);

    // 6. tensor-core (mma.sync tf32x3) conv tower
    conv_mma_kernel<181, 128, 4, 2, 1, 256><<<dim3(64, Bn), 256, SM1>>>(
        feat + (size_t)OFF_VOL * HW, apack + APACK_OFF1, b1, feat + (size_t)OFF_C1 * HW);
    conv_mma_kernel<309, 128, 4, 2, 1, 256><<<dim3(64, Bn), 256, SM1>>>(
        feat + (size_t)OFF_C1 * HW, apack + APACK_OFF2, b2, feat + (size_t)OFF_C2 * HW);
    conv_mma_kernel<437, 96, 3, 2, 1, 192><<<dim3(64, Bn), 192, SM3>>>(
        feat + (size_t)OFF_C2 * HW, apack + APACK_OFF3, b3, feat + (size_t)OFF_C3 * HW);
    conv_mma_kernel<533, 64, 2, 4, 2, 256><<<dim3(32, Bn), 256, SM4>>>(
        feat + (size_t)OFF_C3 * HW, apack + APACK_OFF4, b4, feat + (size_t)OFF_C4 * HW);
    conv_mma_kernel<597, 32, 1, 4, 2, 128><<<dim3(32, Bn), 128, SM5>>>(
        feat + (size_t)OFF_C4 * HW, apack + APACK_OFF5, b5, feat + (size_t)OFF_C5 * HW);

    // 7. conv6 (Cout=2) -> flow, FFMA path
    conv3x3_kernel<2><<<dim3(1, 8, Bn), 256>>>(
        feat + (size_t)OFF_C5 * HW, w6, b6, flow,
        629, FEAT_STRIDE, 2 * HW);
}

// round 6
// speedup vs baseline: 1.9824x; 1.4196x over previous
#include <cuda_runtime.h>
#include <math.h>
#include <stdint.h>

// ---------------------------------------------------------------------------
// Problem dims (fixed by the dataset)
// ---------------------------------------------------------------------------
#define Bn 8
#define H 64
#define W 128
#define HW (H * W)            // 8192
#define C1CH 96               // tenOne / tenTwo channels
#define HIN 32
#define WIN 64
#define HWIN (HIN * WIN)      // 2048
#define PREVC 661

#define FEAT_C 629
#define FEAT_STRIDE (FEAT_C * HW)   // per-batch stride of feat

// channel offsets inside final feat (concats prepend):
// [c5(32) | c4(64) | c3(96) | c2(128) | c1(128) | vol(81) | tenOne(96) | flow(2) | upfeat(2)]
#define OFF_C5   0
#define OFF_C4   32
#define OFF_C3   96
#define OFF_C2   192
#define OFF_C1   320
#define OFF_VOL  448
#define OFF_T1   529
#define OFF_FLOW 625
#define OFF_UPF  627

// scratch: warped tenTwo
__device__ float g_warped[(size_t)Bn * C1CH * HW];

// pre-packed tf32 weight fragments, chunk = 72 k (8 channels x 9 taps)
// u32 per stage: nChunks*9*(Cout/16)*256
#define APACK_OFF1 0
#define APACK_OFF2 423936      // + 23*9*8*256
#define APACK_OFF3 1142784     // + 39*9*8*256
#define APACK_OFF4 1903104     // + 55*9*6*256
#define APACK_OFF5 2520576     // + 67*9*4*256
#define APACK_TOTAL 2866176    // + 75*9*2*256
__device__ uint32_t g_Apack[APACK_TOTAL];

// ---------------------------------------------------------------------------
// helpers
// ---------------------------------------------------------------------------
__device__ __forceinline__ uint32_t f2tf32(float f) {
    uint32_t r;
    asm("cvt.rna.tf32.f32 %0, %1;" : "=r"(r) : "f"(f));
    return r;
}
__device__ __forceinline__ uint32_t smem_u32(const void* p) {
    uint32_t a;
    asm("{ .reg .u64 t; cvta.to.shared.u64 t, %1; cvt.u32.u64 %0, t; }" : "=r"(a) : "l"(p));
    return a;
}
__device__ __forceinline__ void cp_async16(uint32_t dst, const void* src) {
    asm volatile("cp.async.ca.shared.global [%0], [%1], 16;" :: "r"(dst), "l"(src));
}
#define CP_COMMIT() asm volatile("cp.async.commit_group;")
#define CP_WAIT0()  asm volatile("cp.async.wait_group 0;")
#define CP_WAIT1()  asm volatile("cp.async.wait_group 1;")

#define MMA_TF32(c, a, b0v, b1v) \
    asm volatile( \
        "mma.sync.aligned.m16n8k8.row.col.f32.tf32.tf32.f32 " \
        "{%0,%1,%2,%3}, {%4,%5,%6,%7}, {%8,%9}, {%0,%1,%2,%3};" \
        : "+f"((c)[0]), "+f"((c)[1]), "+f"((c)[2]), "+f"((c)[3]) \
        : "r"((a).x), "r"((a).y), "r"((a).z), "r"((a).w), \
          "r"(b0v), "r"(b1v))

// ---------------------------------------------------------------------------
// ConvTranspose2d(k=4, s=2, p=1), Cout = 2
// ---------------------------------------------------------------------------
__global__ void upconv_kernel(const float* __restrict__ in,
                              const float* __restrict__ w,
                              const float* __restrict__ bias,
                              float* __restrict__ out, int Cin)
{
    int gid = blockIdx.x * blockDim.x + threadIdx.x;
    if (gid >= Bn * HW) return;
    int b = gid / HW;
    int pix = gid - b * HW;
    int y = pix / W, x = pix - (pix / W) * W;

    int iy0 = y >> 1,                        ky0 = 1 + (y & 1);
    int iy1 = (y >> 1) + ((y & 1) ? 1 : -1), ky1 = (y & 1) ? 0 : 3;
    int ix0 = x >> 1,                        kx0 = 1 + (x & 1);
    int ix1 = (x >> 1) + ((x & 1) ? 1 : -1), kx1 = (x & 1) ? 0 : 3;
    bool vy1 = (unsigned)iy1 < HIN;
    bool vx1 = (unsigned)ix1 < WIN;

    float a0 = bias[0], a1 = bias[1];
    const float* pin = in + (size_t)b * Cin * HWIN;
    int w00i = ky0 * 4 + kx0, w01i = ky0 * 4 + kx1;
    int w10i = ky1 * 4 + kx0, w11i = ky1 * 4 + kx1;
    int p00 = iy0 * WIN + ix0, p01 = iy0 * WIN + ix1;
    int p10 = iy1 * WIN + ix0, p11 = iy1 * WIN + ix1;

    for (int ci = 0; ci < Cin; ci++) {
        const float* p = pin + (size_t)ci * HWIN;
        const float* wc = w + (size_t)ci * 32;
        float v = p[p00];
        a0 += v * wc[w00i];       a1 += v * wc[16 + w00i];
        if (vx1)        { float u = p[p01]; a0 += u * wc[w01i]; a1 += u * wc[16 + w01i]; }
        if (vy1)        { float u = p[p10]; a0 += u * wc[w10i]; a1 += u * wc[16 + w10i]; }
        if (vy1 && vx1) { float u = p[p11]; a0 += u * wc[w11i]; a1 += u * wc[16 + w11i]; }
    }
    out[(size_t)b * FEAT_STRIDE + pix]      = a0;
    out[(size_t)b * FEAT_STRIDE + HW + pix] = a1;
}

__global__ void copy_t1_kernel(const float* __restrict__ t1, float* __restrict__ feat)
{
    size_t i = (size_t)blockIdx.x * blockDim.x + threadIdx.x;
    const size_t n4 = (size_t)Bn * C1CH * HW / 4;
    if (i >= n4) return;
    const size_t per = (size_t)C1CH * HW / 4;
    size_t b = i / per, r = i - b * per;
    float4 v = ((const float4*)t1)[i];
    ((float4*)(feat + b * (size_t)FEAT_STRIDE + (size_t)OFF_T1 * HW))[r] = v;
}

__global__ void warp_kernel(const float* __restrict__ tenTwo, const float* __restrict__ feat)
{
    int gid = blockIdx.x * blockDim.x + threadIdx.x;
    if (gid >= Bn * HW) return;
    int b = gid / HW;
    int pix = gid - b * HW;
    int y = pix / W, x = pix - (pix / W) * W;

    const float* fl = feat + (size_t)b * FEAT_STRIDE + (size_t)OFF_FLOW * HW + pix;
    float px = (float)x + fl[0]  * 1.25f;
    float py = (float)y + fl[HW] * 1.25f;
    float fx = floorf(px), fy = floorf(py);
    float wx = px - fx, wy = py - fy;
    int ix0 = (int)fx, iy0 = (int)fy;
    int ix1 = ix0 + 1, iy1 = iy0 + 1;
    bool vx0 = (unsigned)ix0 < W, vx1 = (unsigned)ix1 < W;
    bool vy0 = (unsigned)iy0 < H, vy1 = (unsigned)iy1 < H;
    float w00 = (1.f - wy) * (1.f - wx), w01 = (1.f - wy) * wx;
    float w10 = wy * (1.f - wx),         w11 = wy * wx;
    int o00 = iy0 * W + ix0, o01 = iy0 * W + ix1;
    int o10 = iy1 * W + ix0, o11 = iy1 * W + ix1;

    const float* t = tenTwo + (size_t)b * C1CH * HW;
    float* o = g_warped + (size_t)b * C1CH * HW + pix;
    for (int c = 0; c < C1CH; c++) {
        const float* tc = t + (size_t)c * HW;
        float v = 0.f;
        if (vy0 && vx0) v += tc[o00] * w00;
        if (vy0 && vx1) v += tc[o01] * w01;
        if (vy1 && vx0) v += tc[o10] * w10;
        if (vy1 && vx1) v += tc[o11] * w11;
        o[(size_t)c * HW] = v;
    }
}

__global__ __launch_bounds__(128) void corr_kernel(const float* __restrict__ tenOne,
                                                   float* __restrict__ feat)
{
    __shared__ float s_f1[4][32];
    __shared__ float s_w2[12][40];
    int tid = threadIdx.x;
    int tx = tid & 31, ty = tid >> 5;
    int x0 = blockIdx.x * 32, y0 = blockIdx.y * 4, b = blockIdx.z;

    float acc[81];
#pragma unroll
    for (int d = 0; d < 81; d++) acc[d] = 0.f;

    const float* f1 = tenOne + (size_t)b * C1CH * HW;
    const float* f2 = g_warped + (size_t)b * C1CH * HW;

    for (int c = 0; c < C1CH; c++) {
        const float* f1c = f1 + (size_t)c * HW;
        const float* f2c = f2 + (size_t)c * HW;
        __syncthreads();
        s_f1[ty][tx] = f1c[(y0 + ty) * W + x0 + tx];
#pragma unroll
        for (int i = 0; i < 4; i++) {
            int idx = tid + i * 128;
            if (idx < 480) {
                int r = idx / 40, cc = idx - (idx / 40) * 40;
                int gy = y0 - 4 + r, gx = x0 - 4 + cc;
                float v = 0.f;
                if ((unsigned)gy < H && (unsigned)gx < W) v = f2c[gy * W + gx];
                s_w2[r][cc] = v;
            }
        }
        __syncthreads();
        float a = s_f1[ty][tx];
#pragma unroll
        for (int dy = 0; dy < 9; dy++)
#pragma unroll
            for (int dx = 0; dx < 9; dx++)
                acc[dy * 9 + dx] += a * s_w2[ty + dy][tx + dx];
    }

    float* o = feat + (size_t)b * FEAT_STRIDE + (size_t)OFF_VOL * HW + (y0 + ty) * W + x0 + tx;
    const float inv = 1.f / 96.f;
#pragma unroll
    for (int d = 0; d < 81; d++) {
        float v = acc[d] * inv;
        o[(size_t)d * HW] = (v >= 0.f) ? v : 0.1f * v;
    }
}

// ---------------------------------------------------------------------------
// FFMA direct 3x3 conv (kept for conv6, Cout=2)
// ---------------------------------------------------------------------------
template <int COUT_BLK>
__global__ __launch_bounds__(256) void conv3x3_kernel(
    const float* __restrict__ in, const float* __restrict__ w,
    const float* __restrict__ bias, float* __restrict__ out,
    int Cin, int inStride, int outStride)
{
    __shared__ float s_in[18][66];
    __shared__ float s_w[COUT_BLK * 9];
    const int tid = threadIdx.x;
    const int tx = tid & 15, ty = tid >> 4;
    const int g = blockIdx.x;
    const int tileX = blockIdx.y & 1, tileY = blockIdx.y >> 1;
    const int b = blockIdx.z;
    const int x0 = tileX * 64, y0 = tileY * 16;

    const float* inB = in + (size_t)b * inStride;
    float acc[COUT_BLK][4];
#pragma unroll
    for (int c = 0; c < COUT_BLK; c++)
#pragma unroll
        for (int p = 0; p < 4; p++) acc[c][p] = 0.f;

    for (int ci = 0; ci < Cin; ci++) {
        const float* ch = inB + (size_t)ci * HW;
#pragma unroll
        for (int i = 0; i < 5; i++) {
            int idx = tid + i * 256;
            if (idx < 18 * 66) {
                int r = idx / 66, c = idx - (idx / 66) * 66;
                int gy = y0 - 1 + r, gx = x0 - 1 + c;
                float v = 0.f;
                if ((unsigned)gy < H && (unsigned)gx < W) v = ch[gy * W + gx];
                s_in[r][c] = v;
            }
        }
        if (tid < COUT_BLK * 9)
            s_w[tid] = w[((size_t)(g * COUT_BLK + tid / 9) * Cin + ci) * 9 + tid % 9];
        __syncthreads();

        float r0[6], r1[6], r2[6];
#pragma unroll
        for (int k = 0; k < 6; k++) {
            r0[k] = s_in[ty][tx * 4 + k];
            r1[k] = s_in[ty + 1][tx * 4 + k];
            r2[k] = s_in[ty + 2][tx * 4 + k];
        }
#pragma unroll
        for (int co = 0; co < COUT_BLK; co++) {
            float w0 = s_w[co * 9 + 0], w1v = s_w[co * 9 + 1], w2v = s_w[co * 9 + 2];
            float w3v = s_w[co * 9 + 3], w4v = s_w[co * 9 + 4], w5v = s_w[co * 9 + 5];
            float w6v = s_w[co * 9 + 6], w7v = s_w[co * 9 + 7], w8v = s_w[co * 9 + 8];
#pragma unroll
            for (int p = 0; p < 4; p++) {
                float s = acc[co][p];
                s += w0  * r0[p]; s += w1v * r0[p + 1]; s += w2v * r0[p + 2];
                s += w3v * r1[p]; s += w4v * r1[p + 1]; s += w5v * r1[p + 2];
                s += w6v * r2[p]; s += w7v * r2[p + 1]; s += w8v * r2[p + 2];
                acc[co][p] = s;
            }
        }
        __syncthreads();
    }

#pragma unroll
    for (int co = 0; co < COUT_BLK; co++) {
        float bi = bias[g * COUT_BLK + co];
        float* o = out + (size_t)b * outStride + (size_t)(g * COUT_BLK + co) * HW
                 + (y0 + ty) * W + x0 + tx * 4;
#pragma unroll
        for (int p = 0; p < 4; p++) {
            float v = acc[co][p] + bi;
            o[p] = (v >= 0.f) ? v : 0.1f * v;
        }
    }
}

// ---------------------------------------------------------------------------
// Weight pre-pack, chunk = 72 k (8 channels x 9 taps).
// u32 layout: [kt][ks][mf][h(hi/lo)][lane][r]
//   m = mf*16 + (lane>>2) + 8*(r&1),  k = kt*72 + ks*8 + (lane&3) + 4*(r>>1)
// ---------------------------------------------------------------------------
__global__ void pack_weights2_kernel(const float* __restrict__ w, uint32_t* __restrict__ dst,
                                     int Cin, int Cout, int nChunks)
{
    int idx = blockIdx.x * blockDim.x + threadIdx.x;
    int MFT2 = Cout >> 4;
    int total = nChunks * 9 * MFT2 * 256;
    if (idx >= total) return;
    int r = idx & 3, lane = (idx >> 2) & 31, h = (idx >> 7) & 1;
    int u2 = idx >> 8;
    int mf = u2 % MFT2;
    int u3 = u2 / MFT2;
    int ks = u3 % 9, kt = u3 / 9;
    int m = mf * 16 + (lane >> 2) + 8 * (r & 1);
    int k = kt * 72 + ks * 8 + (lane & 3) + 4 * (r >> 1);
    int K = Cin * 9;
    float v = (k < K) ? w[(size_t)m * K + k] : 0.f;
    uint32_t hi = f2tf32(v);
    dst[idx] = h ? f2tf32(v - __uint_as_float(hi)) : hi;
}

// ---------------------------------------------------------------------------
// Implicit-GEMM 3x3 conv via mma.sync m16n8k8 tf32 (3xTF32 split).
// Chunk = 72 k = 8 channels x 9 taps. Raw input rows staged via cp.async
// (double-buffered); im2col + hi/lo split on the fly at fragment read.
// A fragments read directly from pre-packed global (L2-resident).
// Warp tile 32(M) x 64(N). CTA: M = Cout, N = NROWS*128.
// ---------------------------------------------------------------------------
template <int Cin, int Cout, int NW, int NROWS, int THREADS, int MINB>
__global__ __launch_bounds__(THREADS, MINB) void conv_mma2_kernel(
    const float* __restrict__ inBase,
    const uint4* __restrict__ Apack,
    const float* __restrict__ bias,
    float* __restrict__ outBase)
{
    constexpr int nC    = (Cin + 7) / 8;
    constexpr int R     = NROWS + 2;          // staged rows per channel
    constexpr int SROW  = 136;                // floats per staged row (8 mod 32 banks)
    constexpr int BUFSZ = 8 * R * SROW;       // floats per buffer
    constexpr int MFT2  = Cout / 16;

    extern __shared__ float raw[];
    const int tid = threadIdx.x, lane = tid & 31, wrp = tid >> 5;
    const int wm = wrp / NW, wn = wrp % NW;
    const int wm0 = wm * 32, wn0 = wn * 64;
    const int wrow = wn0 >> 7, wcol = wn0 & 127;
    const int yBase = blockIdx.x * NROWS, b = blockIdx.y;
    const float* inB = inBase + (size_t)b * FEAT_STRIDE;
    const uint32_t rawAddr = smem_u32(raw);

    // zero guard columns (cols 3 and 132 of every staged row, both buffers)
    for (int i = tid; i < 2 * 8 * R; i += THREADS) {
        raw[i * SROW + 3]   = 0.f;
        raw[i * SROW + 132] = 0.f;
    }

    float acc[2][8][4];
#pragma unroll
    for (int mi = 0; mi < 2; mi++)
#pragma unroll
        for (int ni = 0; ni < 8; ni++)
#pragma unroll
            for (int p = 0; p < 4; p++) acc[mi][ni][p] = 0.f;

    // ---- staging: copy raw rows (128 floats each) for chunk kt into buffer ----
    auto stage = [&](int kt, int bufsel) {
        const int total = 8 * R * 32;
        for (int i = tid; i < total; i += THREADS) {
            int c   = i / (R * 32);
            int rem = i - c * (R * 32);
            int rr  = rem >> 5, v = rem & 31;
            int ci  = kt * 8 + c;
            int gy  = yBase + rr - 1;
            int foff = bufsel * BUFSZ + (c * R + rr) * SROW + 4 + v * 4;
            if (ci < Cin && (unsigned)gy < (unsigned)H) {
                cp_async16(rawAddr + (uint32_t)(foff * 4),
                           inB + (size_t)ci * HW + gy * W + v * 4);
            } else {
                *(float4*)(raw + foff) = make_float4(0.f, 0.f, 0.f, 0.f);
            }
        }
    };

    stage(0, 0);
    CP_COMMIT();

    for (int kt = 0; kt < nC; kt++) {
        const int buf = kt & 1;
        if (kt + 1 < nC) {
            stage(kt + 1, buf ^ 1);
            CP_COMMIT();
            CP_WAIT1();
        } else {
            CP_WAIT0();
        }
        __syncthreads();

        const float* rb = raw + buf * BUFSZ;
        const uint4* ap = Apack + (size_t)(kt * 9 * MFT2) * 64;
        const int t = lane & 3;
        const int nbase = wcol + (lane >> 2);

#pragma unroll
        for (int ks = 0; ks < 9; ks++) {
            const uint4* apk = ap + (ks * MFT2 + wm * 2) * 64 + lane;
            uint4 ah0 = apk[0];
            uint4 al0 = apk[32];
            uint4 ah1 = apk[64];
            uint4 al1 = apk[96];

            int kb0 = ks * 8 + t, kb1 = kb0 + 4;
            int c0 = kb0 / 9, tp0 = kb0 - c0 * 9;
            int c1 = kb1 / 9, tp1 = kb1 - c1 * 9;
            const float* p0 = rb + (c0 * R + wrow + tp0 / 3) * SROW + (tp0 % 3) + 3 + nbase;
            const float* p1 = rb + (c1 * R + wrow + tp1 / 3) * SROW + (tp1 % 3) + 3 + nbase;

#pragma unroll
            for (int nb = 0; nb < 8; nb += 4) {
                uint32_t bh0[4], bl0[4], bh1[4], bl1[4];
#pragma unroll
                for (int j = 0; j < 4; j++) {
                    float v0 = p0[(nb + j) * 8];
                    float v1 = p1[(nb + j) * 8];
                    bh0[j] = f2tf32(v0); bl0[j] = f2tf32(v0 - __uint_as_float(bh0[j]));
                    bh1[j] = f2tf32(v1); bl1[j] = f2tf32(v1 - __uint_as_float(bh1[j]));
                }
#pragma unroll
                for (int j = 0; j < 4; j++) {
                    MMA_TF32(acc[0][nb + j], ah0, bh0[j], bh1[j]);
                    MMA_TF32(acc[1][nb + j], ah1, bh0[j], bh1[j]);
                }
#pragma unroll
                for (int j = 0; j < 4; j++) {
                    MMA_TF32(acc[0][nb + j], al0, bh0[j], bh1[j]);
                    MMA_TF32(acc[1][nb + j], al1, bh0[j], bh1[j]);
                }
#pragma unroll
                for (int j = 0; j < 4; j++) {
                    MMA_TF32(acc[0][nb + j], ah0, bl0[j], bl1[j]);
                    MMA_TF32(acc[1][nb + j], ah1, bl0[j], bl1[j]);
                }
            }
        }
        __syncthreads();
    }

    // ---- epilogue: bias + leaky, float2 stores ----
    const int q = lane & 3, g = lane >> 2;
    float* outB = outBase + (size_t)b * FEAT_STRIDE;
#pragma unroll
    for (int mi = 0; mi < 2; mi++) {
        int m0 = wm0 + mi * 16 + g;
        float bLo = __ldg(bias + m0), bHi = __ldg(bias + m0 + 8);
        float* o0 = outB + (size_t)m0 * HW;
        float* o1 = o0 + 8 * HW;
#pragma unroll
        for (int ni = 0; ni < 8; ni++) {
            int n = wn0 + ni * 8 + 2 * q;
            int off = (yBase + (n >> 7)) * W + (n & 127);
            float v0 = acc[mi][ni][0] + bLo, v1 = acc[mi][ni][1] + bLo;
            float v2 = acc[mi][ni][2] + bHi, v3 = acc[mi][ni][3] + bHi;
            v0 = (v0 >= 0.f) ? v0 : 0.1f * v0;
            v1 = (v1 >= 0.f) ? v1 : 0.1f * v1;
            v2 = (v2 >= 0.f) ? v2 : 0.1f * v2;
            v3 = (v3 >= 0.f) ? v3 : 0.1f * v3;
            *(float2*)(o0 + off) = make_float2(v0, v1);
            *(float2*)(o1 + off) = make_float2(v2, v3);
        }
    }
}

// ---------------------------------------------------------------------------
// Launch
// ---------------------------------------------------------------------------
extern "C" void kernel_launch(void* const* d_in, const int* in_sizes, int n_in,
                              void* d_out, int out_size)
{
    (void)in_sizes; (void)n_in; (void)out_size;
    const float* tenOne    = (const float*)d_in[0];
    const float* tenTwo    = (const float*)d_in[1];
    const float* prev_flow = (const float*)d_in[2];
    const float* prev_feat = (const float*)d_in[3];
    const float* w_upflow  = (const float*)d_in[4];
    const float* b_upflow  = (const float*)d_in[5];
    const float* w_upfeat  = (const float*)d_in[6];
    const float* b_upfeat  = (const float*)d_in[7];
    const float* w1 = (const float*)d_in[8];   const float* b1 = (const float*)d_in[9];
    const float* w2 = (const float*)d_in[10];  const float* b2 = (const float*)d_in[11];
    const float* w3 = (const float*)d_in[12];  const float* b3 = (const float*)d_in[13];
    const float* w4 = (const float*)d_in[14];  const float* b4 = (const float*)d_in[15];
    const float* w5 = (const float*)d_in[16];  const float* b5 = (const float*)d_in[17];
    const float* w6 = (const float*)d_in[18];  const float* b6 = (const float*)d_in[19];

    float* flow = (float*)d_out;                       // (B, 2, H, W)
    float* feat = flow + (size_t)Bn * 2 * HW;          // (B, 629, H, W)

    uint32_t* apack;
    cudaGetSymbolAddress((void**)&apack, g_Apack);

    const int NPIX = Bn * HW;

    // weight pre-pack
    pack_weights2_kernel<<<(23 * 9 * 8 * 256 + 255) / 256, 256>>>(w1, apack + APACK_OFF1, 181, 128, 23);
    pack_weights2_kernel<<<(39 * 9 * 8 * 256 + 255) / 256, 256>>>(w2, apack + APACK_OFF2, 309, 128, 39);
    pack_weights2_kernel<<<(55 * 9 * 6 * 256 + 255) / 256, 256>>>(w3, apack + APACK_OFF3, 437, 96, 55);
    pack_weights2_kernel<<<(67 * 9 * 4 * 256 + 255) / 256, 256>>>(w4, apack + APACK_OFF4, 533, 64, 67);
    pack_weights2_kernel<<<(75 * 9 * 2 * 256 + 255) / 256, 256>>>(w5, apack + APACK_OFF5, 597, 32, 75);

    // 1-2. upsampled flow / feat
    upconv_kernel<<<(NPIX + 255) / 256, 256>>>(prev_flow, w_upflow, b_upflow,
                                               feat + (size_t)OFF_FLOW * HW, 2);
    upconv_kernel<<<(NPIX + 255) / 256, 256>>>(prev_feat, w_upfeat, b_upfeat,
                                               feat + (size_t)OFF_UPF * HW, PREVC);
    // 3. tenOne -> feat
    {
        size_t n4 = (size_t)Bn * C1CH * HW / 4;
        copy_t1_kernel<<<(unsigned)((n4 + 255) / 256), 256>>>(tenOne, feat);
    }
    // 4. warp tenTwo
    warp_kernel<<<(NPIX + 255) / 256, 256>>>(tenTwo, feat);
    // 5. correlation
    corr_kernel<<<dim3(W / 32, H / 4, Bn), 128>>>(tenOne, feat);

    // 6. tensor-core conv tower (chunk-72 pipeline)
    // smem bytes: NROWS=1 -> 2*8*3*136*4 = 26112 ; NROWS=2 -> 34816
    conv_mma2_kernel<181, 128, 2, 1, 256, 2><<<dim3(64, Bn), 256, 26112>>>(
        feat + (size_t)OFF_VOL * HW, (const uint4*)(apack + APACK_OFF1), b1, feat + (size_t)OFF_C1 * HW);
    conv_mma2_kernel<309, 128, 2, 1, 256, 2><<<dim3(64, Bn), 256, 26112>>>(
        feat + (size_t)OFF_C1 * HW, (const uint4*)(apack + APACK_OFF2), b2, feat + (size_t)OFF_C2 * HW);
    conv_mma2_kernel<437, 96, 2, 1, 192, 2><<<dim3(64, Bn), 192, 26112>>>(
        feat + (size_t)OFF_C2 * HW, (const uint4*)(apack + APACK_OFF3), b3, feat + (size_t)OFF_C3 * HW);
    conv_mma2_kernel<533, 64, 2, 1, 128, 4><<<dim3(64, Bn), 128, 26112>>>(
        feat + (size_t)OFF_C3 * HW, (const uint4*)(apack + APACK_OFF4), b4, feat + (size_t)OFF_C4 * HW);
    conv_mma2_kernel<597, 32, 4, 2, 128, 4><<<dim3(32, Bn), 128, 34816>>>(
        feat + (size_t)OFF_C4 * HW, (const uint4*)(apack + APACK_OFF5), b5, feat + (size_t)OFF_C5 * HW);

    // 7. conv6 (Cout=2) -> flow, FFMA path
    conv3x3_kernel<2><<<dim3(1, 8, Bn), 256>>>(
        feat + (size_t)OFF_C5 * HW, w6, b6, flow,
        629, FEAT_STRIDE, 2 * HW);
}

// round 7
// speedup vs baseline: 2.8702x; 1.4478x over previous
#include <cuda_runtime.h>
#include <cuda_fp16.h>
#include <math.h>
#include <stdint.h>

// ---------------------------------------------------------------------------
// Problem dims (fixed by the dataset)
// ---------------------------------------------------------------------------
#define Bn 8
#define H 64
#define W 128
#define HW (H * W)            // 8192
#define C1CH 96               // tenOne / tenTwo channels
#define HIN 32
#define WIN 64
#define HWIN (HIN * WIN)      // 2048
#define PREVC 661

#define FEAT_C 629
#define FEAT_STRIDE (FEAT_C * HW)   // per-batch stride of feat

// channel offsets inside final feat (concats prepend):
// [c5(32) | c4(64) | c3(96) | c2(128) | c1(128) | vol(81) | tenOne(96) | flow(2) | upfeat(2)]
#define OFF_C5   0
#define OFF_C4   32
#define OFF_C3   96
#define OFF_C2   192
#define OFF_C1   320
#define OFF_VOL  448
#define OFF_T1   529
#define OFF_FLOW 625
#define OFF_UPF  627

// scratch: warped tenTwo
__device__ float g_warped[(size_t)Bn * C1CH * HW];

// packed (h,l) fp16 shadow of feat (u32 per pixel): hi16 = lo-part, lo16 = hi-part
__device__ uint32_t g_half[(size_t)Bn * FEAT_C * HW];

// pre-packed fp16 hi/lo A-fragments, chunk = 144 k (16 channels x 9 taps)
// u32 per stage: nChunks*9*(Cout/16)*256
#define APACK_OFF1 0
#define APACK_OFF2 221184      // + 12*9*8*256
#define APACK_OFF3 589824      // + 20*9*8*256
#define APACK_OFF4 976896      // + 28*9*6*256
#define APACK_OFF5 1290240     // + 34*9*4*256
#define APACK_TOTAL 1465344    // + 38*9*2*256
__device__ uint32_t g_Apack[APACK_TOTAL];

// ---------------------------------------------------------------------------
// helpers
// ---------------------------------------------------------------------------
__device__ __forceinline__ uint32_t smem_u32(const void* p) {
    uint32_t a;
    asm("{ .reg .u64 t; cvta.to.shared.u64 t, %1; cvt.u32.u64 %0, t; }" : "=r"(a) : "l"(p));
    return a;
}
__device__ __forceinline__ void cp_async16(uint32_t dst, const void* src) {
    asm volatile("cp.async.ca.shared.global [%0], [%1], 16;" :: "r"(dst), "l"(src));
}
#define CP_COMMIT() asm volatile("cp.async.commit_group;")
#define CP_WAIT0()  asm volatile("cp.async.wait_group 0;")
#define CP_WAIT1()  asm volatile("cp.async.wait_group 1;")

__device__ __forceinline__ uint32_t packhl(float v) {
    __half h = __float2half_rn(v);
    __half l = __float2half_rn(v - __half2float(h));
    return (uint32_t)__half_as_ushort(h) | ((uint32_t)__half_as_ushort(l) << 16);
}

#define MMA_F16(c, a, b0v, b1v) \
    asm volatile( \
        "mma.sync.aligned.m16n8k16.row.col.f32.f16.f16.f32 " \
        "{%0,%1,%2,%3}, {%4,%5,%6,%7}, {%8,%9}, {%0,%1,%2,%3};" \
        : "+f"((c)[0]), "+f"((c)[1]), "+f"((c)[2]), "+f"((c)[3]) \
        : "r"((a).x), "r"((a).y), "r"((a).z), "r"((a).w), \
          "r"(b0v), "r"(b1v))

// ---------------------------------------------------------------------------
// ConvTranspose2d(k=4, s=2, p=1), Cout = 2
// ---------------------------------------------------------------------------
__global__ void upconv_kernel(const float* __restrict__ in,
                              const float* __restrict__ w,
                              const float* __restrict__ bias,
                              float* __restrict__ out, int Cin)
{
    int gid = blockIdx.x * blockDim.x + threadIdx.x;
    if (gid >= Bn * HW) return;
    int b = gid / HW;
    int pix = gid - b * HW;
    int y = pix / W, x = pix - (pix / W) * W;

    int iy0 = y >> 1,                        ky0 = 1 + (y & 1);
    int iy1 = (y >> 1) + ((y & 1) ? 1 : -1), ky1 = (y & 1) ? 0 : 3;
    int ix0 = x >> 1,                        kx0 = 1 + (x & 1);
    int ix1 = (x >> 1) + ((x & 1) ? 1 : -1), kx1 = (x & 1) ? 0 : 3;
    bool vy1 = (unsigned)iy1 < HIN;
    bool vx1 = (unsigned)ix1 < WIN;

    float a0 = bias[0], a1 = bias[1];
    const float* pin = in + (size_t)b * Cin * HWIN;
    int w00i = ky0 * 4 + kx0, w01i = ky0 * 4 + kx1;
    int w10i = ky1 * 4 + kx0, w11i = ky1 * 4 + kx1;
    int p00 = iy0 * WIN + ix0, p01 = iy0 * WIN + ix1;
    int p10 = iy1 * WIN + ix0, p11 = iy1 * WIN + ix1;

    for (int ci = 0; ci < Cin; ci++) {
        const float* p = pin + (size_t)ci * HWIN;
        const float* wc = w + (size_t)ci * 32;
        float v = p[p00];
        a0 += v * wc[w00i];       a1 += v * wc[16 + w00i];
        if (vx1)        { float u = p[p01]; a0 += u * wc[w01i]; a1 += u * wc[16 + w01i]; }
        if (vy1)        { float u = p[p10]; a0 += u * wc[w10i]; a1 += u * wc[16 + w10i]; }
        if (vy1 && vx1) { float u = p[p11]; a0 += u * wc[w11i]; a1 += u * wc[16 + w11i]; }
    }
    out[(size_t)b * FEAT_STRIDE + pix]      = a0;
    out[(size_t)b * FEAT_STRIDE + HW + pix] = a1;
}

__global__ void copy_t1_kernel(const float* __restrict__ t1, float* __restrict__ feat)
{
    size_t i = (size_t)blockIdx.x * blockDim.x + threadIdx.x;
    const size_t n4 = (size_t)Bn * C1CH * HW / 4;
    if (i >= n4) return;
    const size_t per = (size_t)C1CH * HW / 4;
    size_t b = i / per, r = i - b * per;
    float4 v = ((const float4*)t1)[i];
    ((float4*)(feat + b * (size_t)FEAT_STRIDE + (size_t)OFF_T1 * HW))[r] = v;
}

__global__ void warp_kernel(const float* __restrict__ tenTwo, const float* __restrict__ feat)
{
    int gid = blockIdx.x * blockDim.x + threadIdx.x;
    if (gid >= Bn * HW) return;
    int b = gid / HW;
    int pix = gid - b * HW;
    int y = pix / W, x = pix - (pix / W) * W;

    const float* fl = feat + (size_t)b * FEAT_STRIDE + (size_t)OFF_FLOW * HW + pix;
    float px = (float)x + fl[0]  * 1.25f;
    float py = (float)y + fl[HW] * 1.25f;
    float fx = floorf(px), fy = floorf(py);
    float wx = px - fx, wy = py - fy;
    int ix0 = (int)fx, iy0 = (int)fy;
    int ix1 = ix0 + 1, iy1 = iy0 + 1;
    bool vx0 = (unsigned)ix0 < W, vx1 = (unsigned)ix1 < W;
    bool vy0 = (unsigned)iy0 < H, vy1 = (unsigned)iy1 < H;
    float w00 = (1.f - wy) * (1.f - wx), w01 = (1.f - wy) * wx;
    float w10 = wy * (1.f - wx),         w11 = wy * wx;
    int o00 = iy0 * W + ix0, o01 = iy0 * W + ix1;
    int o10 = iy1 * W + ix0, o11 = iy1 * W + ix1;

    const float* t = tenTwo + (size_t)b * C1CH * HW;
    float* o = g_warped + (size_t)b * C1CH * HW + pix;
    for (int c = 0; c < C1CH; c++) {
        const float* tc = t + (size_t)c * HW;
        float v = 0.f;
        if (vy0 && vx0) v += tc[o00] * w00;
        if (vy0 && vx1) v += tc[o01] * w01;
        if (vy1 && vx0) v += tc[o10] * w10;
        if (vy1 && vx1) v += tc[o11] * w11;
        o[(size_t)c * HW] = v;
    }
}

__global__ __launch_bounds__(128) void corr_kernel(const float* __restrict__ tenOne,
                                                   float* __restrict__ feat)
{
    __shared__ float s_f1[4][32];
    __shared__ float s_w2[12][40];
    int tid = threadIdx.x;
    int tx = tid & 31, ty = tid >> 5;
    int x0 = blockIdx.x * 32, y0 = blockIdx.y * 4, b = blockIdx.z;

    float acc[81];
#pragma unroll
    for (int d = 0; d < 81; d++) acc[d] = 0.f;

    const float* f1 = tenOne + (size_t)b * C1CH * HW;
    const float* f2 = g_warped + (size_t)b * C1CH * HW;

    for (int c = 0; c < C1CH; c++) {
        const float* f1c = f1 + (size_t)c * HW;
        const float* f2c = f2 + (size_t)c * HW;
        __syncthreads();
        s_f1[ty][tx] = f1c[(y0 + ty) * W + x0 + tx];
#pragma unroll
        for (int i = 0; i < 4; i++) {
            int idx = tid + i * 128;
            if (idx < 480) {
                int r = idx / 40, cc = idx - (idx / 40) * 40;
                int gy = y0 - 4 + r, gx = x0 - 4 + cc;
                float v = 0.f;
                if ((unsigned)gy < H && (unsigned)gx < W) v = f2c[gy * W + gx];
                s_w2[r][cc] = v;
            }
        }
        __syncthreads();
        float a = s_f1[ty][tx];
#pragma unroll
        for (int dy = 0; dy < 9; dy++)
#pragma unroll
            for (int dx = 0; dx < 9; dx++)
                acc[dy * 9 + dx] += a * s_w2[ty + dy][tx + dx];
    }

    float* o = feat + (size_t)b * FEAT_STRIDE + (size_t)OFF_VOL * HW + (y0 + ty) * W + x0 + tx;
    const float inv = 1.f / 96.f;
#pragma unroll
    for (int d = 0; d < 81; d++) {
        float v = acc[d] * inv;
        o[(size_t)d * HW] = (v >= 0.f) ? v : 0.1f * v;
    }
}

// ---------------------------------------------------------------------------
// FFMA direct 3x3 conv (kept for conv6, Cout=2)
// ---------------------------------------------------------------------------
template <int COUT_BLK>
__global__ __launch_bounds__(256) void conv3x3_kernel(
    const float* __restrict__ in, const float* __restrict__ w,
    const float* __restrict__ bias, float* __restrict__ out,
    int Cin, int inStride, int outStride)
{
    __shared__ float s_in[18][66];
    __shared__ float s_w[COUT_BLK * 9];
    const int tid = threadIdx.x;
    const int tx = tid & 15, ty = tid >> 4;
    const int g = blockIdx.x;
    const int tileX = blockIdx.y & 1, tileY = blockIdx.y >> 1;
    const int b = blockIdx.z;
    const int x0 = tileX * 64, y0 = tileY * 16;

    const float* inB = in + (size_t)b * inStride;
    float acc[COUT_BLK][4];
#pragma unroll
    for (int c = 0; c < COUT_BLK; c++)
#pragma unroll
        for (int p = 0; p < 4; p++) acc[c][p] = 0.f;

    for (int ci = 0; ci < Cin; ci++) {
        const float* ch = inB + (size_t)ci * HW;
#pragma unroll
        for (int i = 0; i < 5; i++) {
            int idx = tid + i * 256;
            if (idx < 18 * 66) {
                int r = idx / 66, c = idx - (idx / 66) * 66;
                int gy = y0 - 1 + r, gx = x0 - 1 + c;
                float v = 0.f;
                if ((unsigned)gy < H && (unsigned)gx < W) v = ch[gy * W + gx];
                s_in[r][c] = v;
            }
        }
        if (tid < COUT_BLK * 9)
            s_w[tid] = w[((size_t)(g * COUT_BLK + tid / 9) * Cin + ci) * 9 + tid % 9];
        __syncthreads();

        float r0[6], r1[6], r2[6];
#pragma unroll
        for (int k = 0; k < 6; k++) {
            r0[k] = s_in[ty][tx * 4 + k];
            r1[k] = s_in[ty + 1][tx * 4 + k];
            r2[k] = s_in[ty + 2][tx * 4 + k];
        }
#pragma unroll
        for (int co = 0; co < COUT_BLK; co++) {
            float w0 = s_w[co * 9 + 0], w1v = s_w[co * 9 + 1], w2v = s_w[co * 9 + 2];
            float w3v = s_w[co * 9 + 3], w4v = s_w[co * 9 + 4], w5v = s_w[co * 9 + 5];
            float w6v = s_w[co * 9 + 6], w7v = s_w[co * 9 + 7], w8v = s_w[co * 9 + 8];
#pragma unroll
            for (int p = 0; p < 4; p++) {
                float s = acc[co][p];
                s += w0  * r0[p]; s += w1v * r0[p + 1]; s += w2v * r0[p + 2];
                s += w3v * r1[p]; s += w4v * r1[p + 1]; s += w5v * r1[p + 2];
                s += w6v * r2[p]; s += w7v * r2[p + 1]; s += w8v * r2[p + 2];
                acc[co][p] = s;
            }
        }
        __syncthreads();
    }

#pragma unroll
    for (int co = 0; co < COUT_BLK; co++) {
        float bi = bias[g * COUT_BLK + co];
        float* o = out + (size_t)b * outStride + (size_t)(g * COUT_BLK + co) * HW
                 + (y0 + ty) * W + x0 + tx * 4;
#pragma unroll
        for (int p = 0; p < 4; p++) {
            float v = acc[co][p] + bi;
            o[p] = (v >= 0.f) ? v : 0.1f * v;
        }
    }
}

// ---------------------------------------------------------------------------
// Convert the 181 base channels (vol/t1/flow/upf) fp32 -> packed (h,l)
// ---------------------------------------------------------------------------
__global__ void convert_init_kernel(const float* __restrict__ feat, uint32_t* __restrict__ dst)
{
    size_t i = (size_t)blockIdx.x * blockDim.x + threadIdx.x;
    const size_t per = (size_t)181 * HW;
    if (i >= (size_t)Bn * per) return;
    size_t b = i / per, r = i - b * per;
    size_t off = b * (size_t)FEAT_STRIDE + (size_t)OFF_VOL * HW + r;
    dst[off] = packhl(feat[off]);
}

// ---------------------------------------------------------------------------
// Weight pre-pack: fp16 hi/lo m16n8k16 A-fragments, chunk = 144 k.
// u32 idx = ((((kt*9+ks)*MFT + mf)*2 + term)*32 + lane)*4 + reg
//   m = mf*16 + (lane>>2) + 8*(reg&1)
//   k = kt*144 + ks*16 + (lane&3)*2 + 8*(reg>>1)   (pair k, k+1)
// ---------------------------------------------------------------------------
__global__ void pack_weights3_kernel(const float* __restrict__ w, uint32_t* __restrict__ dst,
                                     int Cin, int Cout, int nChunks)
{
    int idx = blockIdx.x * blockDim.x + threadIdx.x;
    int MFT = Cout >> 4;
    int total = nChunks * 9 * MFT * 256;
    if (idx >= total) return;
    int reg = idx & 3, lane = (idx >> 2) & 31, term = (idx >> 7) & 1;
    int u = idx >> 8;
    int mf = u % MFT;
    int v3 = u / MFT;
    int ks = v3 % 9, kt = v3 / 9;
    int m = mf * 16 + (lane >> 2) + 8 * (reg & 1);
    int k = kt * 144 + ks * 16 + (lane & 3) * 2 + 8 * (reg >> 1);
    int K = Cin * 9;
    float v0 = (k     < K) ? w[(size_t)m * K + k]     : 0.f;
    float v1 = (k + 1 < K) ? w[(size_t)m * K + k + 1] : 0.f;
    __half h0 = __float2half_rn(v0), h1 = __float2half_rn(v1);
    uint32_t out;
    if (term == 0) {
        out = (uint32_t)__half_as_ushort(h0) | ((uint32_t)__half_as_ushort(h1) << 16);
    } else {
        __half l0 = __float2half_rn(v0 - __half2float(h0));
        __half l1 = __float2half_rn(v1 - __half2float(h1));
        out = (uint32_t)__half_as_ushort(l0) | ((uint32_t)__half_as_ushort(l1) << 16);
    }
    dst[idx] = out;
}

// ---------------------------------------------------------------------------
// Implicit-GEMM 3x3 conv via mma.sync m16n8k16 fp16 (3-term hi/lo split).
// Chunk = 144 k = 16 channels x 9 taps = 9 k16-steps. Packed (h,l) activation
// rows staged via cp.async (double-buffered); B fragments built with byte_perm.
// A fragments read from pre-packed global. Warp tile 32(M) x 64(N).
// Epilogue dual-writes fp32 feat + packed g_half.
// ---------------------------------------------------------------------------
template <int Cin, int Cout, int NW, int NROWS, int THREADS, int MINB>
__global__ __launch_bounds__(THREADS, MINB) void conv_mma3_kernel(
    const uint32_t* __restrict__ inBase,   // g_half batch-0 ptr at input channel offset
    const uint4* __restrict__ Apack,
    const float* __restrict__ bias,
    float* __restrict__ outBase,           // feat batch-0 ptr at output channel offset
    uint32_t* __restrict__ outHalfBase)    // g_half batch-0 ptr at output channel offset
{
    constexpr int nC    = (Cin + 15) / 16;
    constexpr int R     = NROWS + 2;          // staged rows per channel
    constexpr int SROW  = 136;                // u32 per staged row
    constexpr int BUFSZ = 16 * R * SROW;      // u32 per buffer
    constexpr int MFT   = Cout / 16;

    extern __shared__ uint32_t raw[];
    const int tid = threadIdx.x, lane = tid & 31, wrp = tid >> 5;
    const int wm = wrp / NW, wn = wrp % NW;
    const int wm0 = wm * 32, wn0 = wn * 64;
    const int wrow = wn0 >> 7, wcol = wn0 & 127;
    const int yBase = blockIdx.x * NROWS, b = blockIdx.y;
    const uint32_t* inB = inBase + (size_t)b * FEAT_STRIDE;
    const uint32_t rawAddr = smem_u32(raw);

    // zero guard columns (cols 3 and 132 of every staged row, both buffers)
    for (int i = tid; i < 2 * 16 * R; i += THREADS) {
        raw[i * SROW + 3]   = 0u;
        raw[i * SROW + 132] = 0u;
    }

    float acc[2][8][4];
#pragma unroll
    for (int mi = 0; mi < 2; mi++)
#pragma unroll
        for (int ni = 0; ni < 8; ni++)
#pragma unroll
            for (int p = 0; p < 4; p++) acc[mi][ni][p] = 0.f;

    // ---- staging: copy packed rows (128 u32 each) for chunk kt ----
    auto stage = [&](int kt, int bufsel) {
        const int total = 16 * R * 32;
        for (int i = tid; i < total; i += THREADS) {
            int c   = i / (R * 32);
            int rem = i - c * (R * 32);
            int rr  = rem >> 5, v = rem & 31;
            int ci  = kt * 16 + c;
            int gy  = yBase + rr - 1;
            int foff = bufsel * BUFSZ + (c * R + rr) * SROW + 4 + v * 4;
            if (ci < Cin && (unsigned)gy < (unsigned)H) {
                cp_async16(rawAddr + (uint32_t)(foff * 4),
                           inB + (size_t)ci * HW + gy * W + v * 4);
            } else {
                *(uint4*)(raw + foff) = make_uint4(0u, 0u, 0u, 0u);
            }
        }
    };

    stage(0, 0);
    CP_COMMIT();

    const int t = lane & 3;
    const int nbase = wcol + (lane >> 2);

    for (int kt = 0; kt < nC; kt++) {
        const int buf = kt & 1;
        if (kt + 1 < nC) {
            stage(kt + 1, buf ^ 1);
            CP_COMMIT();
            CP_WAIT1();
        } else {
            CP_WAIT0();
        }
        __syncthreads();

        const uint32_t* rb = raw + buf * BUFSZ;
        const uint4* ap = Apack + (size_t)(kt * 9 + 0) * 0;  // base below per ks
        (void)ap;

#pragma unroll 3
        for (int ks = 0; ks < 9; ks++) {
            const uint4* apk = Apack + (size_t)((kt * 9 + ks) * MFT + wm * 2) * 64 + lane;
            uint4 ah0 = apk[0];
            uint4 al0 = apk[32];
            uint4 ah1 = apk[64];
            uint4 al1 = apk[96];

            // 4 k positions this thread needs: j0, j0+1, j1, j1+1
            int j0 = ks * 16 + 2 * t, j1 = j0 + 8;
            const uint32_t* q0;
            const uint32_t* q1;
            const uint32_t* q2;
            const uint32_t* q3;
            {
                int c = j0 / 9, tp = j0 - c * 9;
                q0 = rb + (c * R + wrow + tp / 3) * SROW + (tp % 3) + 3 + nbase;
            }
            {
                int jj = j0 + 1;
                int c = jj / 9, tp = jj - c * 9;
                q1 = rb + (c * R + wrow + tp / 3) * SROW + (tp % 3) + 3 + nbase;
            }
            {
                int c = j1 / 9, tp = j1 - c * 9;
                q2 = rb + (c * R + wrow + tp / 3) * SROW + (tp % 3) + 3 + nbase;
            }
            {
                int jj = j1 + 1;
                int c = jj / 9, tp = jj - c * 9;
                q3 = rb + (c * R + wrow + tp / 3) * SROW + (tp % 3) + 3 + nbase;
            }

#pragma unroll
            for (int nf = 0; nf < 8; nf++) {
                uint32_t w00 = q0[nf * 8], w01 = q1[nf * 8];
                uint32_t w10 = q2[nf * 8], w11 = q3[nf * 8];
                uint32_t bh0 = __byte_perm(w00, w01, 0x5410);
                uint32_t bl0 = __byte_perm(w00, w01, 0x7632);
                uint32_t bh1 = __byte_perm(w10, w11, 0x5410);
                uint32_t bl1 = __byte_perm(w10, w11, 0x7632);
                MMA_F16(acc[0][nf], ah0, bh0, bh1);
                MMA_F16(acc[1][nf], ah1, bh0, bh1);
                MMA_F16(acc[0][nf], al0, bh0, bh1);
                MMA_F16(acc[1][nf], al1, bh0, bh1);
                MMA_F16(acc[0][nf], ah0, bl0, bl1);
                MMA_F16(acc[1][nf], ah1, bl0, bl1);
            }
        }
        __syncthreads();
    }

    // ---- epilogue: bias + leaky; dual-write fp32 feat + packed g_half ----
    const int q = lane & 3, g2 = lane >> 2;
    float* outB = outBase + (size_t)b * FEAT_STRIDE;
    uint32_t* outH = outHalfBase + (size_t)b * FEAT_STRIDE;
#pragma unroll
    for (int mi = 0; mi < 2; mi++) {
        int m0 = wm0 + mi * 16 + g2;
        float bLo = __ldg(bias + m0), bHi = __ldg(bias + m0 + 8);
        float* o0 = outB + (size_t)m0 * HW;
        float* o1 = o0 + 8 * HW;
        uint32_t* h0 = outH + (size_t)m0 * HW;
        uint32_t* h1 = h0 + 8 * HW;
#pragma unroll
        for (int ni = 0; ni < 8; ni++) {
            int n = wn0 + ni * 8 + 2 * q;
            int off = (yBase + (n >> 7)) * W + (n & 127);
            float v0 = acc[mi][ni][0] + bLo, v1 = acc[mi][ni][1] + bLo;
            float v2 = acc[mi][ni][2] + bHi, v3 = acc[mi][ni][3] + bHi;
            v0 = (v0 >= 0.f) ? v0 : 0.1f * v0;
            v1 = (v1 >= 0.f) ? v1 : 0.1f * v1;
            v2 = (v2 >= 0.f) ? v2 : 0.1f * v2;
            v3 = (v3 >= 0.f) ? v3 : 0.1f * v3;
            *(float2*)(o0 + off) = make_float2(v0, v1);
            *(float2*)(o1 + off) = make_float2(v2, v3);
            *(uint2*)(h0 + off) = make_uint2(packhl(v0), packhl(v1));
            *(uint2*)(h1 + off) = make_uint2(packhl(v2), packhl(v3));
        }
    }
}

// ---------------------------------------------------------------------------
// Launch
// ---------------------------------------------------------------------------
extern "C" void kernel_launch(void* const* d_in, const int* in_sizes, int n_in,
                              void* d_out, int out_size)
{
    (void)in_sizes; (void)n_in; (void)out_size;
    const float* tenOne    = (const float*)d_in[0];
    const float* tenTwo    = (const float*)d_in[1];
    const float* prev_flow = (const float*)d_in[2];
    const float* prev_feat = (const float*)d_in[3];
    const float* w_upflow  = (const float*)d_in[4];
    const float* b_upflow  = (const float*)d_in[5];
    const float* w_upfeat  = (const float*)d_in[6];
    const float* b_upfeat  = (const float*)d_in[7];
    const float* w1 = (const float*)d_in[8];   const float* b1 = (const float*)d_in[9];
    const float* w2 = (const float*)d_in[10];  const float* b2 = (const float*)d_in[11];
    const float* w3 = (const float*)d_in[12];  const float* b3 = (const float*)d_in[13];
    const float* w4 = (const float*)d_in[14];  const float* b4 = (const float*)d_in[15];
    const float* w5 = (const float*)d_in[16];  const float* b5 = (const float*)d_in[17];
    const float* w6 = (const float*)d_in[18];  const float* b6 = (const float*)d_in[19];

    float* flow = (float*)d_out;                       // (B, 2, H, W)
    float* feat = flow + (size_t)Bn * 2 * HW;          // (B, 629, H, W)

    uint32_t* apack;
    cudaGetSymbolAddress((void**)&apack, g_Apack);
    uint32_t* half;
    cudaGetSymbolAddress((void**)&half, g_half);

    // smem bytes: NROWS=1 -> 2*16*3*136*4 = 52224 ; NROWS=2 -> 69632
    const int SMA = 52224, SMB = 69632;
    cudaFuncSetAttribute(conv_mma3_kernel<181, 128, 2, 1, 256, 2>, cudaFuncAttributeMaxDynamicSharedMemorySize, SMA);
    cudaFuncSetAttribute(conv_mma3_kernel<309, 128, 2, 1, 256, 2>, cudaFuncAttributeMaxDynamicSharedMemorySize, SMA);
    cudaFuncSetAttribute(conv_mma3_kernel<437,  96, 2, 1, 192, 2>, cudaFuncAttributeMaxDynamicSharedMemorySize, SMA);
    cudaFuncSetAttribute(conv_mma3_kernel<533,  64, 2, 1, 128, 3>, cudaFuncAttributeMaxDynamicSharedMemorySize, SMA);
    cudaFuncSetAttribute(conv_mma3_kernel<597,  32, 4, 2, 128, 3>, cudaFuncAttributeMaxDynamicSharedMemorySize, SMB);

    const int NPIX = Bn * HW;

    // weight pre-pack
    pack_weights3_kernel<<<(12 * 9 * 8 * 256 + 255) / 256, 256>>>(w1, apack + APACK_OFF1, 181, 128, 12);
    pack_weights3_kernel<<<(20 * 9 * 8 * 256 + 255) / 256, 256>>>(w2, apack + APACK_OFF2, 309, 128, 20);
    pack_weights3_kernel<<<(28 * 9 * 6 * 256 + 255) / 256, 256>>>(w3, apack + APACK_OFF3, 437, 96, 28);
    pack_weights3_kernel<<<(34 * 9 * 4 * 256 + 255) / 256, 256>>>(w4, apack + APACK_OFF4, 533, 64, 34);
    pack_weights3_kernel<<<(38 * 9 * 2 * 256 + 255) / 256, 256>>>(w5, apack + APACK_OFF5, 597, 32, 38);

    // 1-2. upsampled flow / feat
    upconv_kernel<<<(NPIX + 255) / 256, 256>>>(prev_flow, w_upflow, b_upflow,
                                               feat + (size_t)OFF_FLOW * HW, 2);
    upconv_kernel<<<(NPIX + 255) / 256, 256>>>(prev_feat, w_upfeat, b_upfeat,
                                               feat + (size_t)OFF_UPF * HW, PREVC);
    // 3. tenOne -> feat
    {
        size_t n4 = (size_t)Bn * C1CH * HW / 4;
        copy_t1_kernel<<<(unsigned)((n4 + 255) / 256), 256>>>(tenOne, feat);
    }
    // 4. warp tenTwo
    warp_kernel<<<(NPIX + 255) / 256, 256>>>(tenTwo, feat);
    // 5. correlation
    corr_kernel<<<dim3(W / 32, H / 4, Bn), 128>>>(tenOne, feat);
    // 5b. convert base 181 channels to packed fp16 pairs
    {
        size_t n = (size_t)Bn * 181 * HW;
        convert_init_kernel<<<(unsigned)((n + 255) / 256), 256>>>(feat, half);
    }

    // 6. fp16x3 mma conv tower
    conv_mma3_kernel<181, 128, 2, 1, 256, 2><<<dim3(64, Bn), 256, SMA>>>(
        half + (size_t)OFF_VOL * HW, (const uint4*)(apack + APACK_OFF1), b1,
        feat + (size_t)OFF_C1 * HW, half + (size_t)OFF_C1 * HW);
    conv_mma3_kernel<309, 128, 2, 1, 256, 2><<<dim3(64, Bn), 256, SMA>>>(
        half + (size_t)OFF_C1 * HW, (const uint4*)(apack + APACK_OFF2), b2,
        feat + (size_t)OFF_C2 * HW, half + (size_t)OFF_C2 * HW);
    conv_mma3_kernel<437, 96, 2, 1, 192, 2><<<dim3(64, Bn), 192, SMA>>>(
        half + (size_t)OFF_C2 * HW, (const uint4*)(apack + APACK_OFF3), b3,
        feat + (size_t)OFF_C3 * HW, half + (size_t)OFF_C3 * HW);
    conv_mma3_kernel<533, 64, 2, 1, 128, 3><<<dim3(64, Bn), 128, SMA>>>(
        half + (size_t)OFF_C3 * HW, (const uint4*)(apack + APACK_OFF4), b4,
        feat + (size_t)OFF_C4 * HW, half + (size_t)OFF_C4 * HW);
    conv_mma3_kernel<597, 32, 4, 2, 128, 3><<<dim3(32, Bn), 128, SMB>>>(
        half + (size_t)OFF_C4 * HW, (const uint4*)(apack + APACK_OFF5), b5,
        feat + (size_t)OFF_C5 * HW, half + (size_t)OFF_C5 * HW);

    // 7. conv6 (Cout=2) -> flow, FFMA path
    conv3x3_kernel<2><<<dim3(1, 8, Bn), 256>>>(
        feat + (size_t)OFF_C5 * HW, w6, b6, flow,
        629, FEAT_STRIDE, 2 * HW);
}

// round 9
// speedup vs baseline: 3.0538x; 1.0640x over previous
#include <cuda_runtime.h>
#include <cuda_fp16.h>
#include <math.h>
#include <stdint.h>

// ---------------------------------------------------------------------------
// Problem dims (fixed by the dataset)
// ---------------------------------------------------------------------------
#define Bn 8
#define H 64
#define W 128
#define HW (H * W)            // 8192
#define C1CH 96               // tenOne / tenTwo channels
#define HIN 32
#define WIN 64
#define HWIN (HIN * WIN)      // 2048
#define PREVC 661

#define FEAT_C 629
#define FEAT_STRIDE (FEAT_C * HW)   // per-batch stride of feat

// channel offsets inside final feat (concats prepend):
// [c5(32) | c4(64) | c3(96) | c2(128) | c1(128) | vol(81) | tenOne(96) | flow(2) | upfeat(2)]
#define OFF_C5   0
#define OFF_C4   32
#define OFF_C3   96
#define OFF_C2   192
#define OFF_C1   320
#define OFF_VOL  448
#define OFF_T1   529
#define OFF_FLOW 625
#define OFF_UPF  627

// scratch: warped tenTwo
__device__ float g_warped[(size_t)Bn * C1CH * HW];

// packed (h,l) fp16 shadow of feat (u32 per pixel)
__device__ uint32_t g_half[(size_t)Bn * FEAT_C * HW];

// pre-packed fp16 hi/lo A-fragments, chunk = 144 k (16 channels x 9 taps)
#define APACK_OFF1 0
#define APACK_OFF2 221184      // + 12*9*8*256
#define APACK_OFF3 589824      // + 20*9*8*256
#define APACK_OFF4 976896      // + 28*9*6*256
#define APACK_OFF5 1290240     // + 34*9*4*256
#define APACK_TOTAL 1465344    // + 38*9*2*256
__device__ uint32_t g_Apack[APACK_TOTAL];

// ---------------------------------------------------------------------------
// helpers
// ---------------------------------------------------------------------------
__device__ __forceinline__ uint32_t smem_u32(const void* p) {
    uint32_t a;
    asm("{ .reg .u64 t; cvta.to.shared.u64 t, %1; cvt.u32.u64 %0, t; }" : "=r"(a) : "l"(p));
    return a;
}
__device__ __forceinline__ void cp_async16(uint32_t dst, const void* src) {
    asm volatile("cp.async.ca.shared.global [%0], [%1], 16;" :: "r"(dst), "l"(src));
}
#define CP_COMMIT() asm volatile("cp.async.commit_group;")
#define CP_WAIT0()  asm volatile("cp.async.wait_group 0;")
#define CP_WAIT1()  asm volatile("cp.async.wait_group 1;")

__device__ __forceinline__ uint32_t packhl(float v) {
    __half h = __float2half_rn(v);
    __half l = __float2half_rn(v - __half2float(h));
    return (uint32_t)__half_as_ushort(h) | ((uint32_t)__half_as_ushort(l) << 16);
}

#define MMA_F16(c, a, b0v, b1v) \
    asm volatile( \
        "mma.sync.aligned.m16n8k16.row.col.f32.f16.f16.f32 " \
        "{%0,%1,%2,%3}, {%4,%5,%6,%7}, {%8,%9}, {%0,%1,%2,%3};" \
        : "+f"((c)[0]), "+f"((c)[1]), "+f"((c)[2]), "+f"((c)[3]) \
        : "r"((a).x), "r"((a).y), "r"((a).z), "r"((a).w), \
          "r"(b0v), "r"(b1v))

// ---------------------------------------------------------------------------
// Merged weight pre-pack (all 5 stages, one launch).
// u32 idx within a stage = ((((kt*9+ks)*MFT + mf)*2 + term)*32 + lane)*4 + reg
//   m = mf*16 + (lane>>2) + 8*(reg&1)
//   k = kt*144 + ks*16 + (lane&3)*2 + 8*(reg>>1)   (pair k, k+1)
// ---------------------------------------------------------------------------
__device__ __forceinline__ void pack_one(const float* w, uint32_t* dst, int idx,
                                         int Cin, int Cout)
{
    int MFT = Cout >> 4;
    int reg = idx & 3, lane = (idx >> 2) & 31, term = (idx >> 7) & 1;
    int u = idx >> 8;
    int mf = u % MFT;
    int v3 = u / MFT;
    int ks = v3 % 9, kt = v3 / 9;
    int m = mf * 16 + (lane >> 2) + 8 * (reg & 1);
    int k = kt * 144 + ks * 16 + (lane & 3) * 2 + 8 * (reg >> 1);
    int K = Cin * 9;
    float v0 = (k     < K) ? w[(size_t)m * K + k]     : 0.f;
    float v1 = (k + 1 < K) ? w[(size_t)m * K + k + 1] : 0.f;
    __half h0 = __float2half_rn(v0), h1 = __float2half_rn(v1);
    uint32_t out;
    if (term == 0) {
        out = (uint32_t)__half_as_ushort(h0) | ((uint32_t)__half_as_ushort(h1) << 16);
    } else {
        __half l0 = __float2half_rn(v0 - __half2float(h0));
        __half l1 = __float2half_rn(v1 - __half2float(h1));
        out = (uint32_t)__half_as_ushort(l0) | ((uint32_t)__half_as_ushort(l1) << 16);
    }
    dst[idx] = out;
}

__global__ void pack_all_kernel(const float* __restrict__ w1, const float* __restrict__ w2,
                                const float* __restrict__ w3, const float* __restrict__ w4,
                                const float* __restrict__ w5, uint32_t* __restrict__ dst)
{
    int idx = blockIdx.x * blockDim.x + threadIdx.x;
    if (idx >= APACK_TOTAL) return;
    if      (idx < APACK_OFF2) pack_one(w1, dst + APACK_OFF1, idx - APACK_OFF1, 181, 128);
    else if (idx < APACK_OFF3) pack_one(w2, dst + APACK_OFF2, idx - APACK_OFF2, 309, 128);
    else if (idx < APACK_OFF4) pack_one(w3, dst + APACK_OFF3, idx - APACK_OFF3, 437, 96);
    else if (idx < APACK_OFF5) pack_one(w4, dst + APACK_OFF4, idx - APACK_OFF4, 533, 64);
    else                       pack_one(w5, dst + APACK_OFF5, idx - APACK_OFF5, 597, 32);
}

// ---------------------------------------------------------------------------
// Merged ConvTranspose2d(k=4, s=2, p=1), Cout = 2; blockIdx.y selects which.
// Dual-writes fp32 feat + packed g_half.
// ---------------------------------------------------------------------------
__global__ void upconv_both_kernel(const float* __restrict__ inF, const float* __restrict__ wF,
                                   const float* __restrict__ bF,
                                   const float* __restrict__ inU, const float* __restrict__ wU,
                                   const float* __restrict__ bU,
                                   float* __restrict__ feat)
{
    int gid = blockIdx.x * blockDim.x + threadIdx.x;
    if (gid >= Bn * HW) return;
    const int which = blockIdx.y;
    const float* in  = which ? inU : inF;
    const float* w   = which ? wU  : wF;
    const float* bias= which ? bU  : bF;
    const int Cin    = which ? PREVC : 2;
    const int choff  = which ? OFF_UPF : OFF_FLOW;

    int b = gid / HW;
    int pix = gid - b * HW;
    int y = pix / W, x = pix - (pix / W) * W;

    int iy0 = y >> 1,                        ky0 = 1 + (y & 1);
    int iy1 = (y >> 1) + ((y & 1) ? 1 : -1), ky1 = (y & 1) ? 0 : 3;
    int ix0 = x >> 1,                        kx0 = 1 + (x & 1);
    int ix1 = (x >> 1) + ((x & 1) ? 1 : -1), kx1 = (x & 1) ? 0 : 3;
    bool vy1 = (unsigned)iy1 < HIN;
    bool vx1 = (unsigned)ix1 < WIN;

    float a0 = bias[0], a1 = bias[1];
    const float* pin = in + (size_t)b * Cin * HWIN;
    int w00i = ky0 * 4 + kx0, w01i = ky0 * 4 + kx1;
    int w10i = ky1 * 4 + kx0, w11i = ky1 * 4 + kx1;
    int p00 = iy0 * WIN + ix0, p01 = iy0 * WIN + ix1;
    int p10 = iy1 * WIN + ix0, p11 = iy1 * WIN + ix1;

    for (int ci = 0; ci < Cin; ci++) {
        const float* p = pin + (size_t)ci * HWIN;
        const float* wc = w + (size_t)ci * 32;
        float v = p[p00];
        a0 += v * wc[w00i];       a1 += v * wc[16 + w00i];
        if (vx1)        { float u = p[p01]; a0 += u * wc[w01i]; a1 += u * wc[16 + w01i]; }
        if (vy1)        { float u = p[p10]; a0 += u * wc[w10i]; a1 += u * wc[16 + w10i]; }
        if (vy1 && vx1) { float u = p[p11]; a0 += u * wc[w11i]; a1 += u * wc[16 + w11i]; }
    }
    size_t o = (size_t)b * FEAT_STRIDE + (size_t)choff * HW + pix;
    feat[o]      = a0;
    feat[o + HW] = a1;
    g_half[o]      = packhl(a0);
    g_half[o + HW] = packhl(a1);
}

// ---------------------------------------------------------------------------
// tenOne -> feat slice + packed shadow
// ---------------------------------------------------------------------------
__global__ void copy_t1_kernel(const float* __restrict__ t1, float* __restrict__ feat)
{
    size_t i = (size_t)blockIdx.x * blockDim.x + threadIdx.x;
    const size_t n4 = (size_t)Bn * C1CH * HW / 4;
    if (i >= n4) return;
    const size_t per = (size_t)C1CH * HW / 4;
    size_t b = i / per, r = i - b * per;
    float4 v = ((const float4*)t1)[i];
    size_t o = b * (size_t)FEAT_STRIDE + (size_t)OFF_T1 * HW;
    ((float4*)(feat + o))[r] = v;
    ((uint4*)(g_half + o))[r] = make_uint4(packhl(v.x), packhl(v.y), packhl(v.z), packhl(v.w));
}

__global__ void warp_kernel(const float* __restrict__ tenTwo, const float* __restrict__ feat)
{
    int gid = blockIdx.x * blockDim.x + threadIdx.x;
    if (gid >= Bn * HW) return;
    int b = gid / HW;
    int pix = gid - b * HW;
    int y = pix / W, x = pix - (pix / W) * W;

    const float* fl = feat + (size_t)b * FEAT_STRIDE + (size_t)OFF_FLOW * HW + pix;
    float px = (float)x + fl[0]  * 1.25f;
    float py = (float)y + fl[HW] * 1.25f;
    float fx = floorf(px), fy = floorf(py);
    float wx = px - fx, wy = py - fy;
    int ix0 = (int)fx, iy0 = (int)fy;
    int ix1 = ix0 + 1, iy1 = iy0 + 1;
    bool vx0 = (unsigned)ix0 < W, vx1 = (unsigned)ix1 < W;
    bool vy0 = (unsigned)iy0 < H, vy1 = (unsigned)iy1 < H;
    float w00 = (1.f - wy) * (1.f - wx), w01 = (1.f - wy) * wx;
    float w10 = wy * (1.f - wx),         w11 = wy * wx;
    int o00 = iy0 * W + ix0, o01 = iy0 * W + ix1;
    int o10 = iy1 * W + ix0, o11 = iy1 * W + ix1;

    const float* t = tenTwo + (size_t)b * C1CH * HW;
    float* o = g_warped + (size_t)b * C1CH * HW + pix;
    for (int c = 0; c < C1CH; c++) {
        const float* tc = t + (size_t)c * HW;
        float v = 0.f;
        if (vy0 && vx0) v += tc[o00] * w00;
        if (vy0 && vx1) v += tc[o01] * w01;
        if (vy1 && vx0) v += tc[o10] * w10;
        if (vy1 && vx1) v += tc[o11] * w11;
        o[(size_t)c * HW] = v;
    }
}

// correlation + leaky -> feat vol slice + packed shadow
__global__ __launch_bounds__(128) void corr_kernel(const float* __restrict__ tenOne,
                                                   float* __restrict__ feat)
{
    __shared__ float s_f1[4][32];
    __shared__ float s_w2[12][40];
    int tid = threadIdx.x;
    int tx = tid & 31, ty = tid >> 5;
    int x0 = blockIdx.x * 32, y0 = blockIdx.y * 4, b = blockIdx.z;

    float acc[81];
#pragma unroll
    for (int d = 0; d < 81; d++) acc[d] = 0.f;

    const float* f1 = tenOne + (size_t)b * C1CH * HW;
    const float* f2 = g_warped + (size_t)b * C1CH * HW;

    for (int c = 0; c < C1CH; c++) {
        const float* f1c = f1 + (size_t)c * HW;
        const float* f2c = f2 + (size_t)c * HW;
        __syncthreads();
        s_f1[ty][tx] = f1c[(y0 + ty) * W + x0 + tx];
#pragma unroll
        for (int i = 0; i < 4; i++) {
            int idx = tid + i * 128;
            if (idx < 480) {
                int r = idx / 40, cc = idx - (idx / 40) * 40;
                int gy = y0 - 4 + r, gx = x0 - 4 + cc;
                float v = 0.f;
                if ((unsigned)gy < H && (unsigned)gx < W) v = f2c[gy * W + gx];
                s_w2[r][cc] = v;
            }
        }
        __syncthreads();
        float a = s_f1[ty][tx];
#pragma unroll
        for (int dy = 0; dy < 9; dy++)
#pragma unroll
            for (int dx = 0; dx < 9; dx++)
                acc[dy * 9 + dx] += a * s_w2[ty + dy][tx + dx];
    }

    size_t obase = (size_t)b * FEAT_STRIDE + (size_t)OFF_VOL * HW + (y0 + ty) * W + x0 + tx;
    const float inv = 1.f / 96.f;
#pragma unroll
    for (int d = 0; d < 81; d++) {
        float v = acc[d] * inv;
        v = (v >= 0.f) ? v : 0.1f * v;
        feat[obase + (size_t)d * HW] = v;
        g_half[obase + (size_t)d * HW] = packhl(v);
    }
}

// ---------------------------------------------------------------------------
// FFMA direct 3x3 conv (kept for conv6, Cout=2)
// ---------------------------------------------------------------------------
template <int COUT_BLK>
__global__ __launch_bounds__(256) void conv3x3_kernel(
    const float* __restrict__ in, const float* __restrict__ w,
    const float* __restrict__ bias, float* __restrict__ out,
    int Cin, int inStride, int outStride)
{
    __shared__ float s_in[18][66];
    __shared__ float s_w[COUT_BLK * 9];
    const int tid = threadIdx.x;
    const int tx = tid & 15, ty = tid >> 4;
    const int g = blockIdx.x;
    const int tileX = blockIdx.y & 1, tileY = blockIdx.y >> 1;
    const int b = blockIdx.z;
    const int x0 = tileX * 64, y0 = tileY * 16;

    const float* inB = in + (size_t)b * inStride;
    float acc[COUT_BLK][4];
#pragma unroll
    for (int c = 0; c < COUT_BLK; c++)
#pragma unroll
        for (int p = 0; p < 4; p++) acc[c][p] = 0.f;

    for (int ci = 0; ci < Cin; ci++) {
        const float* ch = inB + (size_t)ci * HW;
#pragma unroll
        for (int i = 0; i < 5; i++) {
            int idx = tid + i * 256;
            if (idx < 18 * 66) {
                int r = idx / 66, c = idx - (idx / 66) * 66;
                int gy = y0 - 1 + r, gx = x0 - 1 + c;
                float v = 0.f;
                if ((unsigned)gy < H && (unsigned)gx < W) v = ch[gy * W + gx];
                s_in[r][c] = v;
            }
        }
        if (tid < COUT_BLK * 9)
            s_w[tid] = w[((size_t)(g * COUT_BLK + tid / 9) * Cin + ci) * 9 + tid % 9];
        __syncthreads();

        float r0[6], r1[6], r2[6];
#pragma unroll
        for (int k = 0; k < 6; k++) {
            r0[k] = s_in[ty][tx * 4 + k];
            r1[k] = s_in[ty + 1][tx * 4 + k];
            r2[k] = s_in[ty + 2][tx * 4 + k];
        }
#pragma unroll
        for (int co = 0; co < COUT_BLK; co++) {
            float w0 = s_w[co * 9 + 0], w1v = s_w[co * 9 + 1], w2v = s_w[co * 9 + 2];
            float w3v = s_w[co * 9 + 3], w4v = s_w[co * 9 + 4], w5v = s_w[co * 9 + 5];
            float w6v = s_w[co * 9 + 6], w7v = s_w[co * 9 + 7], w8v = s_w[co * 9 + 8];
#pragma unroll
            for (int p = 0; p < 4; p++) {
                float s = acc[co][p];
                s += w0  * r0[p]; s += w1v * r0[p + 1]; s += w2v * r0[p + 2];
                s += w3v * r1[p]; s += w4v * r1[p + 1]; s += w5v * r1[p + 2];
                s += w6v * r2[p]; s += w7v * r2[p + 1]; s += w8v * r2[p + 2];
                acc[co][p] = s;
            }
        }
        __syncthreads();
    }

#pragma unroll
    for (int co = 0; co < COUT_BLK; co++) {
        float bi = bias[g * COUT_BLK + co];
        float* o = out + (size_t)b * outStride + (size_t)(g * COUT_BLK + co) * HW
                 + (y0 + ty) * W + x0 + tx * 4;
#pragma unroll
        for (int p = 0; p < 4; p++) {
            float v = acc[co][p] + bi;
            o[p] = (v >= 0.f) ? v : 0.1f * v;
        }
    }
}

// ---------------------------------------------------------------------------
// Implicit-GEMM 3x3 conv via mma.sync m16n8k16 fp16 (3-term hi/lo split).
// Chunk = 144 k = 16 channels x 9 taps. Packed activation rows staged via
// cp.async (double-buffered). A fragments software-pipelined over ks (loaded
// one k-step ahead from pre-packed global -> L2 latency hidden).
// Warp tile 32(M) x 64(N). Epilogue dual-writes fp32 feat + packed g_half.
// ---------------------------------------------------------------------------
template <int Cin, int Cout, int NW, int NROWS, int THREADS, int MINB>
__global__ __launch_bounds__(THREADS, MINB) void conv_mma3_kernel(
    const uint32_t* __restrict__ inBase,
    const uint4* __restrict__ Apack,
    const float* __restrict__ bias,
    float* __restrict__ outBase,
    uint32_t* __restrict__ outHalfBase)
{
    constexpr int nC    = (Cin + 15) / 16;
    constexpr int R     = NROWS + 2;
    constexpr int SROW  = 136;
    constexpr int BUFSZ = 16 * R * SROW;
    constexpr int MFT   = Cout / 16;

    extern __shared__ uint32_t raw[];
    const int tid = threadIdx.x, lane = tid & 31, wrp = tid >> 5;
    const int wm = wrp / NW, wn = wrp % NW;
    const int wm0 = wm * 32, wn0 = wn * 64;
    const int wrow = wn0 >> 7, wcol = wn0 & 127;
    const int yBase = blockIdx.x * NROWS, b = blockIdx.y;
    const uint32_t* inB = inBase + (size_t)b * FEAT_STRIDE;
    const uint32_t rawAddr = smem_u32(raw);

    // warp-local A pointer (mf = wm*2 + mi), offset per (kt,ks) added below
    const uint4* apw = Apack + (size_t)(wm * 2) * 64 + lane;

    for (int i = tid; i < 2 * 16 * R; i += THREADS) {
        raw[i * SROW + 3]   = 0u;
        raw[i * SROW + 132] = 0u;
    }

    float acc[2][8][4];
#pragma unroll
    for (int mi = 0; mi < 2; mi++)
#pragma unroll
        for (int ni = 0; ni < 8; ni++)
#pragma unroll
            for (int p = 0; p < 4; p++) acc[mi][ni][p] = 0.f;

    auto stage = [&](int kt, int bufsel) {
        const int total = 16 * R * 32;
        for (int i = tid; i < total; i += THREADS) {
            int c   = i / (R * 32);
            int rem = i - c * (R * 32);
            int rr  = rem >> 5, v = rem & 31;
            int ci  = kt * 16 + c;
            int gy  = yBase + rr - 1;
            int foff = bufsel * BUFSZ + (c * R + rr) * SROW + 4 + v * 4;
            if (ci < Cin && (unsigned)gy < (unsigned)H) {
                cp_async16(rawAddr + (uint32_t)(foff * 4),
                           inB + (size_t)ci * HW + gy * W + v * 4);
            } else {
                *(uint4*)(raw + foff) = make_uint4(0u, 0u, 0u, 0u);
            }
        }
    };

    stage(0, 0);
    CP_COMMIT();

    const int t = lane & 3;
    const int nbase = wcol + (lane >> 2);

    // A software pipeline: preload (kt=0, ks=0)
    uint4 ah0, al0, ah1, al1;
    {
        const uint4* p = apw;
        ah0 = p[0]; al0 = p[32]; ah1 = p[64]; al1 = p[96];
    }

    for (int kt = 0; kt < nC; kt++) {
        const int buf = kt & 1;
        if (kt + 1 < nC) {
            stage(kt + 1, buf ^ 1);
            CP_COMMIT();
            CP_WAIT1();
        } else {
            CP_WAIT0();
        }
        __syncthreads();

        const uint32_t* rb = raw + buf * BUFSZ;

#pragma unroll
        for (int ks = 0; ks < 9; ks++) {
            // prefetch next A fragment set (next ks, or next chunk's ks0)
            uint4 nh0, nl0, nh1, nl1;
            {
                int nkt = kt, nks = ks + 1;
                if (nks == 9) { nkt = kt + 1; nks = 0; }
                if (nkt < nC) {
                    const uint4* p = apw + (size_t)((nkt * 9 + nks) * MFT) * 64;
                    nh0 = p[0]; nl0 = p[32]; nh1 = p[64]; nl1 = p[96];
                } else {
                    nh0 = nl0 = nh1 = nl1 = make_uint4(0u, 0u, 0u, 0u);
                }
            }

            int j0 = ks * 16 + 2 * t, j1 = j0 + 8;
            const uint32_t* q0;
            const uint32_t* q1;
            const uint32_t* q2;
            const uint32_t* q3;
            {
                int c = j0 / 9, tp = j0 - c * 9;
                q0 = rb + (c * R + wrow + tp / 3) * SROW + (tp % 3) + 3 + nbase;
            }
            {
                int jj = j0 + 1;
                int c = jj / 9, tp = jj - c * 9;
                q1 = rb + (c * R + wrow + tp / 3) * SROW + (tp % 3) + 3 + nbase;
            }
            {
                int c = j1 / 9, tp = j1 - c * 9;
                q2 = rb + (c * R + wrow + tp / 3) * SROW + (tp % 3) + 3 + nbase;
            }
            {
                int jj = j1 + 1;
                int c = jj / 9, tp = jj - c * 9;
                q3 = rb + (c * R + wrow + tp / 3) * SROW + (tp % 3) + 3 + nbase;
            }

#pragma unroll
            for (int nf = 0; nf < 8; nf++) {
                uint32_t w00 = q0[nf * 8], w01 = q1[nf * 8];
                uint32_t w10 = q2[nf * 8], w11 = q3[nf * 8];
                uint32_t bh0 = __byte_perm(w00, w01, 0x5410);
                uint32_t bl0 = __byte_perm(w00, w01, 0x7632);
                uint32_t bh1 = __byte_perm(w10, w11, 0x5410);
                uint32_t bl1 = __byte_perm(w10, w11, 0x7632);
                MMA_F16(acc[0][nf], ah0, bh0, bh1);
                MMA_F16(acc[1][nf], ah1, bh0, bh1);
                MMA_F16(acc[0][nf], al0, bh0, bh1);
                MMA_F16(acc[1][nf], al1, bh0, bh1);
                MMA_F16(acc[0][nf], ah0, bl0, bl1);
                MMA_F16(acc[1][nf], ah1, bl0, bl1);
            }
            ah0 = nh0; al0 = nl0; ah1 = nh1; al1 = nl1;
        }
        __syncthreads();
    }

    // ---- epilogue: bias + leaky; dual-write fp32 feat + packed g_half ----
    const int q = lane & 3, g2 = lane >> 2;
    float* outB = outBase + (size_t)b * FEAT_STRIDE;
    uint32_t* outH = outHalfBase + (size_t)b * FEAT_STRIDE;
#pragma unroll
    for (int mi = 0; mi < 2; mi++) {
        int m0 = wm0 + mi * 16 + g2;
        float bLo = __ldg(bias + m0), bHi = __ldg(bias + m0 + 8);
        float* o0 = outB + (size_t)m0 * HW;
        float* o1 = o0 + 8 * HW;
        uint32_t* h0 = outH + (size_t)m0 * HW;
        uint32_t* h1 = h0 + 8 * HW;
#pragma unroll
        for (int ni = 0; ni < 8; ni++) {
            int n = wn0 + ni * 8 + 2 * q;
            int off = (yBase + (n >> 7)) * W + (n & 127);
            float v0 = acc[mi][ni][0] + bLo, v1 = acc[mi][ni][1] + bLo;
            float v2 = acc[mi][ni][2] + bHi, v3 = acc[mi][ni][3] + bHi;
            v0 = (v0 >= 0.f) ? v0 : 0.1f * v0;
            v1 = (v1 >= 0.f) ? v1 : 0.1f * v1;
            v2 = (v2 >= 0.f) ? v2 : 0.1f * v2;
            v3 = (v3 >= 0.f) ? v3 : 0.1f * v3;
            *(float2*)(o0 + off) = make_float2(v0, v1);
            *(float2*)(o1 + off) = make_float2(v2, v3);
            *(uint2*)(h0 + off) = make_uint2(packhl(v0), packhl(v1));
            *(uint2*)(h1 + off) = make_uint2(packhl(v2), packhl(v3));
        }
    }
}

// ---------------------------------------------------------------------------
// Launch
// ---------------------------------------------------------------------------
extern "C" void kernel_launch(void* const* d_in, const int* in_sizes, int n_in,
                              void* d_out, int out_size)
{
    (void)in_sizes; (void)n_in; (void)out_size;
    const float* tenOne    = (const float*)d_in[0];
    const float* tenTwo    = (const float*)d_in[1];
    const float* prev_flow = (const float*)d_in[2];
    const float* prev_feat = (const float*)d_in[3];
    const float* w_upflow  = (const float*)d_in[4];
    const float* b_upflow  = (const float*)d_in[5];
    const float* w_upfeat  = (const float*)d_in[6];
    const float* b_upfeat  = (const float*)d_in[7];
    const float* w1 = (const float*)d_in[8];   const float* b1 = (const float*)d_in[9];
    const float* w2 = (const float*)d_in[10];  const float* b2 = (const float*)d_in[11];
    const float* w3 = (const float*)d_in[12];  const float* b3 = (const float*)d_in[13];
    const float* w4 = (const float*)d_in[14];  const float* b4 = (const float*)d_in[15];
    const float* w5 = (const float*)d_in[16];  const float* b5 = (const float*)d_in[17];
    const float* w6 = (const float*)d_in[18];  const float* b6 = (const float*)d_in[19];

    float* flow = (float*)d_out;
    float* feat = flow + (size_t)Bn * 2 * HW;

    uint32_t* apack;
    cudaGetSymbolAddress((void**)&apack, g_Apack);
    uint32_t* half;
    cudaGetSymbolAddress((void**)&half, g_half);

    const int SMA = 52224, SMB = 69632;
    cudaFuncSetAttribute(conv_mma3_kernel<181, 128, 2, 1, 256, 2>, cudaFuncAttributeMaxDynamicSharedMemorySize, SMA);
    cudaFuncSetAttribute(conv_mma3_kernel<309, 128, 2, 1, 256, 2>, cudaFuncAttributeMaxDynamicSharedMemorySize, SMA);
    cudaFuncSetAttribute(conv_mma3_kernel<437,  96, 2, 1, 192, 2>, cudaFuncAttributeMaxDynamicSharedMemorySize, SMA);
    cudaFuncSetAttribute(conv_mma3_kernel<533,  64, 2, 1, 128, 3>, cudaFuncAttributeMaxDynamicSharedMemorySize, SMA);
    cudaFuncSetAttribute(conv_mma3_kernel<597,  32, 4, 2, 128, 3>, cudaFuncAttributeMaxDynamicSharedMemorySize, SMB);

    const int NPIX = Bn * HW;

    // 0. merged weight pre-pack
    pack_all_kernel<<<(APACK_TOTAL + 255) / 256, 256>>>(w1, w2, w3, w4, w5, apack);
    // 1. both upconvs (dual-write)
    upconv_both_kernel<<<dim3((NPIX + 255) / 256, 2), 256>>>(
        prev_flow, w_upflow, b_upflow, prev_feat, w_upfeat, b_upfeat, feat);
    // 2. tenOne (dual-write)
    {
        size_t n4 = (size_t)Bn * C1CH * HW / 4;
        copy_t1_kernel<<<(unsigned)((n4 + 255) / 256), 256>>>(tenOne, feat);
    }
    // 3. warp tenTwo
    warp_kernel<<<(NPIX + 255) / 256, 256>>>(tenTwo, feat);
    // 4. correlation (dual-write)
    corr_kernel<<<dim3(W / 32, H / 4, Bn), 128>>>(tenOne, feat);

    // 5-9. fp16x3 mma conv tower
    conv_mma3_kernel<181, 128, 2, 1, 256, 2><<<dim3(64, Bn), 256, SMA>>>(
        half + (size_t)OFF_VOL * HW, (const uint4*)(apack + APACK_OFF1), b1,
        feat + (size_t)OFF_C1 * HW, half + (size_t)OFF_C1 * HW);
    conv_mma3_kernel<309, 128, 2, 1, 256, 2><<<dim3(64, Bn), 256, SMA>>>(
        half + (size_t)OFF_C1 * HW, (const uint4*)(apack + APACK_OFF2), b2,
        feat + (size_t)OFF_C2 * HW, half + (size_t)OFF_C2 * HW);
    conv_mma3_kernel<437, 96, 2, 1, 192, 2><<<dim3(64, Bn), 192, SMA>>>(
        half + (size_t)OFF_C2 * HW, (const uint4*)(apack + APACK_OFF3), b3,
        feat + (size_t)OFF_C3 * HW, half + (size_t)OFF_C3 * HW);
    conv_mma3_kernel<533, 64, 2, 1, 128, 3><<<dim3(64, Bn), 128, SMA>>>(
        half + (size_t)OFF_C3 * HW, (const uint4*)(apack + APACK_OFF4), b4,
        feat + (size_t)OFF_C4 * HW, half + (size_t)OFF_C4 * HW);
    conv_mma3_kernel<597, 32, 4, 2, 128, 3><<<dim3(32, Bn), 128, SMB>>>(
        half + (size_t)OFF_C4 * HW, (const uint4*)(apack + APACK_OFF5), b5,
        feat + (size_t)OFF_C5 * HW, half + (size_t)OFF_C5 * HW);

    // 10. conv6 (Cout=2) -> flow, FFMA path
    conv3x3_kernel<2><<<dim3(1, 8, Bn), 256>>>(
        feat + (size_t)OFF_C5 * HW, w6, b6, flow,
        629, FEAT_STRIDE, 2 * HW);
}

// round 10
// speedup vs baseline: 3.5493x; 1.1622x over previous
#include <cuda_runtime.h>
#include <cuda_fp16.h>
#include <math.h>
#include <stdint.h>

// ---------------------------------------------------------------------------
// Problem dims (fixed by the dataset)
// ---------------------------------------------------------------------------
#define Bn 8
#define H 64
#define W 128
#define HW (H * W)            // 8192
#define C1CH 96               // tenOne / tenTwo channels
#define HIN 32
#define WIN 64
#define HWIN (HIN * WIN)      // 2048
#define PREVC 661

#define FEAT_C 629
#define FEAT_STRIDE (FEAT_C * HW)   // per-batch stride of feat

// channel offsets inside final feat (concats prepend):
// [c5(32) | c4(64) | c3(96) | c2(128) | c1(128) | vol(81) | tenOne(96) | flow(2) | upfeat(2)]
#define OFF_C5   0
#define OFF_C4   32
#define OFF_C3   96
#define OFF_C2   192
#define OFF_C1   320
#define OFF_VOL  448
#define OFF_T1   529
#define OFF_FLOW 625
#define OFF_UPF  627

// scratch: warped tenTwo
__device__ float g_warped[(size_t)Bn * C1CH * HW];

// packed (h,l) fp16 shadow of feat (u32 per pixel)
__device__ uint32_t g_half[(size_t)Bn * FEAT_C * HW];

// pre-packed fp16 (hi only) A-fragments, chunk = 144 k (16 channels x 9 taps)
// u32 per stage: nChunks*9*MFT*128
#define APACK_OFF1 0
#define APACK_OFF2 110592      // + 12*9*8*128
#define APACK_OFF3 294912      // + 20*9*8*128
#define APACK_OFF4 488448      // + 28*9*6*128
#define APACK_OFF5 645120      // + 34*9*4*128
#define APACK_TOTAL 732672     // + 38*9*2*128
__device__ uint32_t g_Apack[APACK_TOTAL];

// ---------------------------------------------------------------------------
// helpers
// ---------------------------------------------------------------------------
__device__ __forceinline__ uint32_t smem_u32(const void* p) {
    uint32_t a;
    asm("{ .reg .u64 t; cvta.to.shared.u64 t, %1; cvt.u32.u64 %0, t; }" : "=r"(a) : "l"(p));
    return a;
}
__device__ __forceinline__ void cp_async16(uint32_t dst, const void* src) {
    asm volatile("cp.async.ca.shared.global [%0], [%1], 16;" :: "r"(dst), "l"(src));
}
#define CP_COMMIT() asm volatile("cp.async.commit_group;")
#define CP_WAIT0()  asm volatile("cp.async.wait_group 0;")
#define CP_WAIT1()  asm volatile("cp.async.wait_group 1;")

__device__ __forceinline__ uint32_t packhl(float v) {
    __half h = __float2half_rn(v);
    __half l = __float2half_rn(v - __half2float(h));
    return (uint32_t)__half_as_ushort(h) | ((uint32_t)__half_as_ushort(l) << 16);
}

#define MMA_F16(c, a0, a1, a2, a3, b0v, b1v) \
    asm volatile( \
        "mma.sync.aligned.m16n8k16.row.col.f32.f16.f16.f32 " \
        "{%0,%1,%2,%3}, {%4,%5,%6,%7}, {%8,%9}, {%0,%1,%2,%3};" \
        : "+f"((c)[0]), "+f"((c)[1]), "+f"((c)[2]), "+f"((c)[3]) \
        : "r"(a0), "r"(a1), "r"(a2), "r"(a3), \
          "r"(b0v), "r"(b1v))

// ---------------------------------------------------------------------------
// Merged weight pre-pack (all 5 stages, one launch), hi fp16 only.
// u32 idx within a stage = (((kt*9+ks)*MFT + mf)*32 + lane)*4 + reg
//   m = mf*16 + (lane>>2) + 8*(reg&1)
//   k = kt*144 + ks*16 + (lane&3)*2 + 8*(reg>>1)   (pair k, k+1)
// ---------------------------------------------------------------------------
__device__ __forceinline__ void pack_one(const float* w, uint32_t* dst, int idx,
                                         int Cin, int Cout)
{
    int MFT = Cout >> 4;
    int reg = idx & 3, lane = (idx >> 2) & 31;
    int u = idx >> 7;
    int mf = u % MFT;
    int v3 = u / MFT;
    int ks = v3 % 9, kt = v3 / 9;
    int m = mf * 16 + (lane >> 2) + 8 * (reg & 1);
    int k = kt * 144 + ks * 16 + (lane & 3) * 2 + 8 * (reg >> 1);
    int K = Cin * 9;
    float v0 = (k     < K) ? w[(size_t)m * K + k]     : 0.f;
    float v1 = (k + 1 < K) ? w[(size_t)m * K + k + 1] : 0.f;
    __half h0 = __float2half_rn(v0), h1 = __float2half_rn(v1);
    dst[idx] = (uint32_t)__half_as_ushort(h0) | ((uint32_t)__half_as_ushort(h1) << 16);
}

__global__ void pack_all_kernel(const float* __restrict__ w1, const float* __restrict__ w2,
                                const float* __restrict__ w3, const float* __restrict__ w4,
                                const float* __restrict__ w5, uint32_t* __restrict__ dst)
{
    int idx = blockIdx.x * blockDim.x + threadIdx.x;
    if (idx >= APACK_TOTAL) return;
    if      (idx < APACK_OFF2) pack_one(w1, dst + APACK_OFF1, idx - APACK_OFF1, 181, 128);
    else if (idx < APACK_OFF3) pack_one(w2, dst + APACK_OFF2, idx - APACK_OFF2, 309, 128);
    else if (idx < APACK_OFF4) pack_one(w3, dst + APACK_OFF3, idx - APACK_OFF3, 437, 96);
    else if (idx < APACK_OFF5) pack_one(w4, dst + APACK_OFF4, idx - APACK_OFF4, 533, 64);
    else                       pack_one(w5, dst + APACK_OFF5, idx - APACK_OFF5, 597, 32);
}

// ---------------------------------------------------------------------------
// Merged ConvTranspose2d(k=4, s=2, p=1), Cout = 2; blockIdx.y selects which.
// Dual-writes fp32 feat + packed g_half.
// ---------------------------------------------------------------------------
__global__ void upconv_both_kernel(const float* __restrict__ inF, const float* __restrict__ wF,
                                   const float* __restrict__ bF,
                                   const float* __restrict__ inU, const float* __restrict__ wU,
                                   const float* __restrict__ bU,
                                   float* __restrict__ feat)
{
    int gid = blockIdx.x * blockDim.x + threadIdx.x;
    if (gid >= Bn * HW) return;
    const int which = blockIdx.y;
    const float* in  = which ? inU : inF;
    const float* w   = which ? wU  : wF;
    const float* bias= which ? bU  : bF;
    const int Cin    = which ? PREVC : 2;
    const int choff  = which ? OFF_UPF : OFF_FLOW;

    int b = gid / HW;
    int pix = gid - b * HW;
    int y = pix / W, x = pix - (pix / W) * W;

    int iy0 = y >> 1,                        ky0 = 1 + (y & 1);
    int iy1 = (y >> 1) + ((y & 1) ? 1 : -1), ky1 = (y & 1) ? 0 : 3;
    int ix0 = x >> 1,                        kx0 = 1 + (x & 1);
    int ix1 = (x >> 1) + ((x & 1) ? 1 : -1), kx1 = (x & 1) ? 0 : 3;
    bool vy1 = (unsigned)iy1 < HIN;
    bool vx1 = (unsigned)ix1 < WIN;

    float a0 = bias[0], a1 = bias[1];
    const float* pin = in + (size_t)b * Cin * HWIN;
    int w00i = ky0 * 4 + kx0, w01i = ky0 * 4 + kx1;
    int w10i = ky1 * 4 + kx0, w11i = ky1 * 4 + kx1;
    int p00 = iy0 * WIN + ix0, p01 = iy0 * WIN + ix1;
    int p10 = iy1 * WIN + ix0, p11 = iy1 * WIN + ix1;

    for (int ci = 0; ci < Cin; ci++) {
        const float* p = pin + (size_t)ci * HWIN;
        const float* wc = w + (size_t)ci * 32;
        float v = p[p00];
        a0 += v * wc[w00i];       a1 += v * wc[16 + w00i];
        if (vx1)        { float u = p[p01]; a0 += u * wc[w01i]; a1 += u * wc[16 + w01i]; }
        if (vy1)        { float u = p[p10]; a0 += u * wc[w10i]; a1 += u * wc[16 + w10i]; }
        if (vy1 && vx1) { float u = p[p11]; a0 += u * wc[w11i]; a1 += u * wc[16 + w11i]; }
    }
    size_t o = (size_t)b * FEAT_STRIDE + (size_t)choff * HW + pix;
    feat[o]      = a0;
    feat[o + HW] = a1;
    g_half[o]      = packhl(a0);
    g_half[o + HW] = packhl(a1);
}

// ---------------------------------------------------------------------------
// tenOne -> feat slice + packed shadow
// ---------------------------------------------------------------------------
__global__ void copy_t1_kernel(const float* __restrict__ t1, float* __restrict__ feat)
{
    size_t i = (size_t)blockIdx.x * blockDim.x + threadIdx.x;
    const size_t n4 = (size_t)Bn * C1CH * HW / 4;
    if (i >= n4) return;
    const size_t per = (size_t)C1CH * HW / 4;
    size_t b = i / per, r = i - b * per;
    float4 v = ((const float4*)t1)[i];
    size_t o = b * (size_t)FEAT_STRIDE + (size_t)OFF_T1 * HW;
    ((float4*)(feat + o))[r] = v;
    ((uint4*)(g_half + o))[r] = make_uint4(packhl(v.x), packhl(v.y), packhl(v.z), packhl(v.w));
}

__global__ void warp_kernel(const float* __restrict__ tenTwo, const float* __restrict__ feat)
{
    int gid = blockIdx.x * blockDim.x + threadIdx.x;
    if (gid >= Bn * HW) return;
    int b = gid / HW;
    int pix = gid - b * HW;
    int y = pix / W, x = pix - (pix / W) * W;

    const float* fl = feat + (size_t)b * FEAT_STRIDE + (size_t)OFF_FLOW * HW + pix;
    float px = (float)x + fl[0]  * 1.25f;
    float py = (float)y + fl[HW] * 1.25f;
    float fx = floorf(px), fy = floorf(py);
    float wx = px - fx, wy = py - fy;
    int ix0 = (int)fx, iy0 = (int)fy;
    int ix1 = ix0 + 1, iy1 = iy0 + 1;
    bool vx0 = (unsigned)ix0 < W, vx1 = (unsigned)ix1 < W;
    bool vy0 = (unsigned)iy0 < H, vy1 = (unsigned)iy1 < H;
    float w00 = (1.f - wy) * (1.f - wx), w01 = (1.f - wy) * wx;
    float w10 = wy * (1.f - wx),         w11 = wy * wx;
    int o00 = iy0 * W + ix0, o01 = iy0 * W + ix1;
    int o10 = iy1 * W + ix0, o11 = iy1 * W + ix1;

    const float* t = tenTwo + (size_t)b * C1CH * HW;
    float* o = g_warped + (size_t)b * C1CH * HW + pix;
    for (int c = 0; c < C1CH; c++) {
        const float* tc = t + (size_t)c * HW;
        float v = 0.f;
        if (vy0 && vx0) v += tc[o00] * w00;
        if (vy0 && vx1) v += tc[o01] * w01;
        if (vy1 && vx0) v += tc[o10] * w10;
        if (vy1 && vx1) v += tc[o11] * w11;
        o[(size_t)c * HW] = v;
    }
}

// correlation + leaky -> feat vol slice + packed shadow
__global__ __launch_bounds__(128) void corr_kernel(const float* __restrict__ tenOne,
                                                   float* __restrict__ feat)
{
    __shared__ float s_f1[4][32];
    __shared__ float s_w2[12][40];
    int tid = threadIdx.x;
    int tx = tid & 31, ty = tid >> 5;
    int x0 = blockIdx.x * 32, y0 = blockIdx.y * 4, b = blockIdx.z;

    float acc[81];
#pragma unroll
    for (int d = 0; d < 81; d++) acc[d] = 0.f;

    const float* f1 = tenOne + (size_t)b * C1CH * HW;
    const float* f2 = g_warped + (size_t)b * C1CH * HW;

    for (int c = 0; c < C1CH; c++) {
        const float* f1c = f1 + (size_t)c * HW;
        const float* f2c = f2 + (size_t)c * HW;
        __syncthreads();
        s_f1[ty][tx] = f1c[(y0 + ty) * W + x0 + tx];
#pragma unroll
        for (int i = 0; i < 4; i++) {
            int idx = tid + i * 128;
            if (idx < 480) {
                int r = idx / 40, cc = idx - (idx / 40) * 40;
                int gy = y0 - 4 + r, gx = x0 - 4 + cc;
                float v = 0.f;
                if ((unsigned)gy < H && (unsigned)gx < W) v = f2c[gy * W + gx];
                s_w2[r][cc] = v;
            }
        }
        __syncthreads();
        float a = s_f1[ty][tx];
#pragma unroll
        for (int dy = 0; dy < 9; dy++)
#pragma unroll
            for (int dx = 0; dx < 9; dx++)
                acc[dy * 9 + dx] += a * s_w2[ty + dy][tx + dx];
    }

    size_t obase = (size_t)b * FEAT_STRIDE + (size_t)OFF_VOL * HW + (y0 + ty) * W + x0 + tx;
    const float inv = 1.f / 96.f;
#pragma unroll
    for (int d = 0; d < 81; d++) {
        float v = acc[d] * inv;
        v = (v >= 0.f) ? v : 0.1f * v;
        feat[obase + (size_t)d * HW] = v;
        g_half[obase + (size_t)d * HW] = packhl(v);
    }
}

// ---------------------------------------------------------------------------
// FFMA direct 3x3 conv (kept for conv6, Cout=2)
// ---------------------------------------------------------------------------
template <int COUT_BLK>
__global__ __launch_bounds__(256) void conv3x3_kernel(
    const float* __restrict__ in, const float* __restrict__ w,
    const float* __restrict__ bias, float* __restrict__ out,
    int Cin, int inStride, int outStride)
{
    __shared__ float s_in[18][66];
    __shared__ float s_w[COUT_BLK * 9];
    const int tid = threadIdx.x;
    const int tx = tid & 15, ty = tid >> 4;
    const int g = blockIdx.x;
    const int tileX = blockIdx.y & 1, tileY = blockIdx.y >> 1;
    const int b = blockIdx.z;
    const int x0 = tileX * 64, y0 = tileY * 16;

    const float* inB = in + (size_t)b * inStride;
    float acc[COUT_BLK][4];
#pragma unroll
    for (int c = 0; c < COUT_BLK; c++)
#pragma unroll
        for (int p = 0; p < 4; p++) acc[c][p] = 0.f;

    for (int ci = 0; ci < Cin; ci++) {
        const float* ch = inB + (size_t)ci * HW;
#pragma unroll
        for (int i = 0; i < 5; i++) {
            int idx = tid + i * 256;
            if (idx < 18 * 66) {
                int r = idx / 66, c = idx - (idx / 66) * 66;
                int gy = y0 - 1 + r, gx = x0 - 1 + c;
                float v = 0.f;
                if ((unsigned)gy < H && (unsigned)gx < W) v = ch[gy * W + gx];
                s_in[r][c] = v;
            }
        }
        if (tid < COUT_BLK * 9)
            s_w[tid] = w[((size_t)(g * COUT_BLK + tid / 9) * Cin + ci) * 9 + tid % 9];
        __syncthreads();

        float r0[6], r1[6], r2[6];
#pragma unroll
        for (int k = 0; k < 6; k++) {
            r0[k] = s_in[ty][tx * 4 + k];
            r1[k] = s_in[ty + 1][tx * 4 + k];
            r2[k] = s_in[ty + 2][tx * 4 + k];
        }
#pragma unroll
        for (int co = 0; co < COUT_BLK; co++) {
            float w0 = s_w[co * 9 + 0], w1v = s_w[co * 9 + 1], w2v = s_w[co * 9 + 2];
            float w3v = s_w[co * 9 + 3], w4v = s_w[co * 9 + 4], w5v = s_w[co * 9 + 5];
            float w6v = s_w[co * 9 + 6], w7v = s_w[co * 9 + 7], w8v = s_w[co * 9 + 8];
#pragma unroll
            for (int p = 0; p < 4; p++) {
                float s = acc[co][p];
                s += w0  * r0[p]; s += w1v * r0[p + 1]; s += w2v * r0[p + 2];
                s += w3v * r1[p]; s += w4v * r1[p + 1]; s += w5v * r1[p + 2];
                s += w6v * r2[p]; s += w7v * r2[p + 1]; s += w8v * r2[p + 2];
                acc[co][p] = s;
            }
        }
        __syncthreads();
    }

#pragma unroll
    for (int co = 0; co < COUT_BLK; co++) {
        float bi = bias[g * COUT_BLK + co];
        float* o = out + (size_t)b * outStride + (size_t)(g * COUT_BLK + co) * HW
                 + (y0 + ty) * W + x0 + tx * 4;
#pragma unroll
        for (int p = 0; p < 4; p++) {
            float v = acc[co][p] + bi;
            o[p] = (v >= 0.f) ? v : 0.1f * v;
        }
    }
}

// ---------------------------------------------------------------------------
// Implicit-GEMM 3x3 conv via mma.sync m16n8k16 fp16, 2-term split:
//   D = w_h·x_h + w_h·x_l   (weight fp16-rounded; activation hi/lo split)
// Chunk = 144 k = 16 channels x 9 taps. Packed activation rows staged via
// cp.async (double-buffered). A (hi) fragments software-pipelined over ks.
// Warp tile 32(M) x 64(N). Epilogue dual-writes fp32 feat + packed g_half.
// ---------------------------------------------------------------------------
template <int Cin, int Cout, int NW, int NROWS, int THREADS, int MINB>
__global__ __launch_bounds__(THREADS, MINB) void conv_mma3_kernel(
    const uint32_t* __restrict__ inBase,
    const uint4* __restrict__ Apack,
    const float* __restrict__ bias,
    float* __restrict__ outBase,
    uint32_t* __restrict__ outHalfBase)
{
    constexpr int nC    = (Cin + 15) / 16;
    constexpr int R     = NROWS + 2;
    constexpr int SROW  = 136;
    constexpr int BUFSZ = 16 * R * SROW;
    constexpr int MFT   = Cout / 16;

    extern __shared__ uint32_t raw[];
    const int tid = threadIdx.x, lane = tid & 31, wrp = tid >> 5;
    const int wm = wrp / NW, wn = wrp % NW;
    const int wm0 = wm * 32, wn0 = wn * 64;
    const int wrow = wn0 >> 7, wcol = wn0 & 127;
    const int yBase = blockIdx.x * NROWS, b = blockIdx.y;
    const uint32_t* inB = inBase + (size_t)b * FEAT_STRIDE;
    const uint32_t rawAddr = smem_u32(raw);

    // warp-local A pointer (mf = wm*2 + mi); per-mf stride = 32 uint4
    const uint4* apw = Apack + (size_t)(wm * 2) * 32 + lane;

    for (int i = tid; i < 2 * 16 * R; i += THREADS) {
        raw[i * SROW + 3]   = 0u;
        raw[i * SROW + 132] = 0u;
    }

    float acc[2][8][4];
#pragma unroll
    for (int mi = 0; mi < 2; mi++)
#pragma unroll
        for (int ni = 0; ni < 8; ni++)
#pragma unroll
            for (int p = 0; p < 4; p++) acc[mi][ni][p] = 0.f;

    auto stage = [&](int kt, int bufsel) {
        const int total = 16 * R * 32;
        for (int i = tid; i < total; i += THREADS) {
            int c   = i / (R * 32);
            int rem = i - c * (R * 32);
            int rr  = rem >> 5, v = rem & 31;
            int ci  = kt * 16 + c;
            int gy  = yBase + rr - 1;
            int foff = bufsel * BUFSZ + (c * R + rr) * SROW + 4 + v * 4;
            if (ci < Cin && (unsigned)gy < (unsigned)H) {
                cp_async16(rawAddr + (uint32_t)(foff * 4),
                           inB + (size_t)ci * HW + gy * W + v * 4);
            } else {
                *(uint4*)(raw + foff) = make_uint4(0u, 0u, 0u, 0u);
            }
        }
    };

    stage(0, 0);
    CP_COMMIT();

    const int t = lane & 3;
    const int nbase = wcol + (lane >> 2);

    // A software pipeline: preload (kt=0, ks=0)
    uint4 ah0, ah1;
    {
        const uint4* p = apw;
        ah0 = p[0]; ah1 = p[32];
    }

    for (int kt = 0; kt < nC; kt++) {
        const int buf = kt & 1;
        if (kt + 1 < nC) {
            stage(kt + 1, buf ^ 1);
            CP_COMMIT();
            CP_WAIT1();
        } else {
            CP_WAIT0();
        }
        __syncthreads();

        const uint32_t* rb = raw + buf * BUFSZ;

#pragma unroll
        for (int ks = 0; ks < 9; ks++) {
            // prefetch next A fragment set (next ks, or next chunk's ks0)
            uint4 nh0, nh1;
            {
                int nkt = kt, nks = ks + 1;
                if (nks == 9) { nkt = kt + 1; nks = 0; }
                if (nkt < nC) {
                    const uint4* p = apw + (size_t)((nkt * 9 + nks) * MFT) * 32;
                    nh0 = p[0]; nh1 = p[32];
                } else {
                    nh0 = nh1 = make_uint4(0u, 0u, 0u, 0u);
                }
            }

            int j0 = ks * 16 + 2 * t, j1 = j0 + 8;
            const uint32_t* q0;
            const uint32_t* q1;
            const uint32_t* q2;
            const uint32_t* q3;
            {
                int c = j0 / 9, tp = j0 - c * 9;
                q0 = rb + (c * R + wrow + tp / 3) * SROW + (tp % 3) + 3 + nbase;
            }
            {
                int jj = j0 + 1;
                int c = jj / 9, tp = jj - c * 9;
                q1 = rb + (c * R + wrow + tp / 3) * SROW + (tp % 3) + 3 + nbase;
            }
            {
                int c = j1 / 9, tp = j1 - c * 9;
                q2 = rb + (c * R + wrow + tp / 3) * SROW + (tp % 3) + 3 + nbase;
            }
            {
                int jj = j1 + 1;
                int c = jj / 9, tp = jj - c * 9;
                q3 = rb + (c * R + wrow + tp / 3) * SROW + (tp % 3) + 3 + nbase;
            }

#pragma unroll
            for (int nf = 0; nf < 8; nf++) {
                uint32_t w00 = q0[nf * 8], w01 = q1[nf * 8];
                uint32_t w10 = q2[nf * 8], w11 = q3[nf * 8];
                uint32_t bh0 = __byte_perm(w00, w01, 0x5410);
                uint32_t bl0 = __byte_perm(w00, w01, 0x7632);
                uint32_t bh1 = __byte_perm(w10, w11, 0x5410);
                uint32_t bl1 = __byte_perm(w10, w11, 0x7632);
                MMA_F16(acc[0][nf], ah0.x, ah0.y, ah0.z, ah0.w, bh0, bh1);
                MMA_F16(acc[1][nf], ah1.x, ah1.y, ah1.z, ah1.w, bh0, bh1);
                MMA_F16(acc[0][nf], ah0.x, ah0.y, ah0.z, ah0.w, bl0, bl1);
                MMA_F16(acc[1][nf], ah1.x, ah1.y, ah1.z, ah1.w, bl0, bl1);
            }
            ah0 = nh0; ah1 = nh1;
        }
        __syncthreads();
    }

    // ---- epilogue: bias + leaky; dual-write fp32 feat + packed g_half ----
    const int q = lane & 3, g2 = lane >> 2;
    float* outB = outBase + (size_t)b * FEAT_STRIDE;
    uint32_t* outH = outHalfBase + (size_t)b * FEAT_STRIDE;
#pragma unroll
    for (int mi = 0; mi < 2; mi++) {
        int m0 = wm0 + mi * 16 + g2;
        float bLo = __ldg(bias + m0), bHi = __ldg(bias + m0 + 8);
        float* o0 = outB + (size_t)m0 * HW;
        float* o1 = o0 + 8 * HW;
        uint32_t* h0 = outH + (size_t)m0 * HW;
        uint32_t* h1 = h0 + 8 * HW;
#pragma unroll
        for (int ni = 0; ni < 8; ni++) {
            int n = wn0 + ni * 8 + 2 * q;
            int off = (yBase + (n >> 7)) * W + (n & 127);
            float v0 = acc[mi][ni][0] + bLo, v1 = acc[mi][ni][1] + bLo;
            float v2 = acc[mi][ni][2] + bHi, v3 = acc[mi][ni][3] + bHi;
            v0 = (v0 >= 0.f) ? v0 : 0.1f * v0;
            v1 = (v1 >= 0.f) ? v1 : 0.1f * v1;
            v2 = (v2 >= 0.f) ? v2 : 0.1f * v2;
            v3 = (v3 >= 0.f) ? v3 : 0.1f * v3;
            *(float2*)(o0 + off) = make_float2(v0, v1);
            *(float2*)(o1 + off) = make_float2(v2, v3);
            *(uint2*)(h0 + off) = make_uint2(packhl(v0), packhl(v1));
            *(uint2*)(h1 + off) = make_uint2(packhl(v2), packhl(v3));
        }
    }
}

// ---------------------------------------------------------------------------
// Launch
// ---------------------------------------------------------------------------
extern "C" void kernel_launch(void* const* d_in, const int* in_sizes, int n_in,
                              void* d_out, int out_size)
{
    (void)in_sizes; (void)n_in; (void)out_size;
    const float* tenOne    = (const float*)d_in[0];
    const float* tenTwo    = (const float*)d_in[1];
    const float* prev_flow = (const float*)d_in[2];
    const float* prev_feat = (const float*)d_in[3];
    const float* w_upflow  = (const float*)d_in[4];
    const float* b_upflow  = (const float*)d_in[5];
    const float* w_upfeat  = (const float*)d_in[6];
    const float* b_upfeat  = (const float*)d_in[7];
    const float* w1 = (const float*)d_in[8];   const float* b1 = (const float*)d_in[9];
    const float* w2 = (const float*)d_in[10];  const float* b2 = (const float*)d_in[11];
    const float* w3 = (const float*)d_in[12];  const float* b3 = (const float*)d_in[13];
    const float* w4 = (const float*)d_in[14];  const float* b4 = (const float*)d_in[15];
    const float* w5 = (const float*)d_in[16];  const float* b5 = (const float*)d_in[17];
    const float* w6 = (const float*)d_in[18];  const float* b6 = (const float*)d_in[19];

    float* flow = (float*)d_out;
    float* feat = flow + (size_t)Bn * 2 * HW;

    uint32_t* apack;
    cudaGetSymbolAddress((void**)&apack, g_Apack);
    uint32_t* half;
    cudaGetSymbolAddress((void**)&half, g_half);

    const int SMA = 52224, SMB = 69632;
    cudaFuncSetAttribute(conv_mma3_kernel<181, 128, 2, 1, 256, 2>, cudaFuncAttributeMaxDynamicSharedMemorySize, SMA);
    cudaFuncSetAttribute(conv_mma3_kernel<309, 128, 2, 1, 256, 2>, cudaFuncAttributeMaxDynamicSharedMemorySize, SMA);
    cudaFuncSetAttribute(conv_mma3_kernel<437,  96, 2, 1, 192, 2>, cudaFuncAttributeMaxDynamicSharedMemorySize, SMA);
    cudaFuncSetAttribute(conv_mma3_kernel<533,  64, 2, 1, 128, 3>, cudaFuncAttributeMaxDynamicSharedMemorySize, SMA);
    cudaFuncSetAttribute(conv_mma3_kernel<597,  32, 4, 2, 128, 3>, cudaFuncAttributeMaxDynamicSharedMemorySize, SMB);

    const int NPIX = Bn * HW;

    // 0. merged weight pre-pack
    pack_all_kernel<<<(APACK_TOTAL + 255) / 256, 256>>>(w1, w2, w3, w4, w5, apack);
    // 1. both upconvs (dual-write)
    upconv_both_kernel<<<dim3((NPIX + 255) / 256, 2), 256>>>(
        prev_flow, w_upflow, b_upflow, prev_feat, w_upfeat, b_upfeat, feat);
    // 2. tenOne (dual-write)
    {
        size_t n4 = (size_t)Bn * C1CH * HW / 4;
        copy_t1_kernel<<<(unsigned)((n4 + 255) / 256), 256>>>(tenOne, feat);
    }
    // 3. warp tenTwo
    warp_kernel<<<(NPIX + 255) / 256, 256>>>(tenTwo, feat);
    // 4. correlation (dual-write)
    corr_kernel<<<dim3(W / 32, H / 4, Bn), 128>>>(tenOne, feat);

    // 5-9. fp16 2-term mma conv tower
    conv_mma3_kernel<181, 128, 2, 1, 256, 2><<<dim3(64, Bn), 256, SMA>>>(
        half + (size_t)OFF_VOL * HW, (const uint4*)(apack + APACK_OFF1), b1,
        feat + (size_t)OFF_C1 * HW, half + (size_t)OFF_C1 * HW);
    conv_mma3_kernel<309, 128, 2, 1, 256, 2><<<dim3(64, Bn), 256, SMA>>>(
        half + (size_t)OFF_C1 * HW, (const uint4*)(apack + APACK_OFF2), b2,
        feat + (size_t)OFF_C2 * HW, half + (size_t)OFF_C2 * HW);
    conv_mma3_kernel<437, 96, 2, 1, 192, 2><<<dim3(64, Bn), 192, SMA>>>(
        half + (size_t)OFF_C2 * HW, (const uint4*)(apack + APACK_OFF3), b3,
        feat + (size_t)OFF_C3 * HW, half + (size_t)OFF_C3 * HW);
    conv_mma3_kernel<533, 64, 2, 1, 128, 3><<<dim3(64, Bn), 128, SMA>>>(
        half + (size_t)OFF_C3 * HW, (const uint4*)(apack + APACK_OFF4), b4,
        feat + (size_t)OFF_C4 * HW, half + (size_t)OFF_C4 * HW);
    conv_mma3_kernel<597, 32, 4, 2, 128, 3><<<dim3(32, Bn), 128, SMB>>>(
        half + (size_t)OFF_C4 * HW, (const uint4*)(apack + APACK_OFF5), b5,
        feat + (size_t)OFF_C5 * HW, half + (size_t)OFF_C5 * HW);

    // 10. conv6 (Cout=2) -> flow, FFMA path
    conv3x3_kernel<2><<<dim3(1, 8, Bn), 256>>>(
        feat + (size_t)OFF_C5 * HW, w6, b6, flow,
        629, FEAT_STRIDE, 2 * HW);
}